// round 10
// baseline (speedup 1.0000x reference)
#include <cuda_runtime.h>
#include <cuda_bf16.h>
#include <math.h>
#include <stdint.h>

// Problem constants
#define B_SZ 8
#define T_SZ 2048
#define C_SZ 1024
#define H_SZ 64
#define WIN 64
#define NGLOB 64
#define NRAND 64

#define BT (B_SZ * T_SZ)          // 16384 rows

// Scratch for projected q, k, v  (4 MB each) — device globals, no allocation.
__device__ float g_Q[BT * H_SZ];
__device__ float g_K[BT * H_SZ];
__device__ float g_V[BT * H_SZ];

__device__ __forceinline__ void mma_bf16(float* c, const uint32_t* a, const uint32_t* b) {
    asm volatile(
        "mma.sync.aligned.m16n8k16.row.col.f32.bf16.bf16.f32 "
        "{%0,%1,%2,%3}, {%4,%5,%6,%7}, {%8,%9}, {%0,%1,%2,%3};"
        : "+f"(c[0]), "+f"(c[1]), "+f"(c[2]), "+f"(c[3])
        : "r"(a[0]), "r"(a[1]), "r"(a[2]), "r"(a[3]),
          "r"(b[0]), "r"(b[1]));
}

// ---------------------------------------------------------------------------
// FUSED projection GEMM (Q,K,V), bf16 3-split, ping-pong smem (UNCHANGED).
// ---------------------------------------------------------------------------
#define KC 16
#define PADK 12
#define NCHUNK (C_SZ / KC)        // 64

__global__ __launch_bounds__(256, 2) void proj_tc_kernel(
    const float* __restrict__ x,
    const float* __restrict__ Wq,
    const float* __restrict__ Wk,
    const float* __restrict__ Wv)
{
    __shared__ __align__(16) uint32_t sm_h[2][256][PADK];
    __shared__ __align__(16) uint32_t sm_l[2][256][PADK];

    const int m0   = blockIdx.x * 64;
    const int tid  = threadIdx.x;
    const int warp = tid >> 5;
    const int lane = tid & 31;
    const int grp  = lane >> 2;   // 0..7
    const int tig  = lane & 3;    // 0..3
    const int mh   = warp & 1;    // M half (32 rows)
    const int nq   = warp >> 1;   // N quarter (6 n-tiles)

    const float* srcs[8];
    int rp[8];
#pragma unroll
    for (int it = 0; it < 8; it++) {
        const int i = it * 256 + tid;
        int r, w;
        const float* base;
        if (it < 2) {
            r = i >> 3; w = i & 7;
            base = &x[(size_t)(m0 + r) * C_SZ];
            rp[it] = r * PADK;
        } else {
            const int j = i - 512;
            r = j >> 3; w = j & 7;
            base = (r < 64)  ? &Wq[(size_t)r * C_SZ]
                 : (r < 128) ? &Wk[(size_t)(r - 64) * C_SZ]
                             : &Wv[(size_t)(r - 128) * C_SZ];
            rp[it] = (64 + r) * PADK;
        }
        srcs[it] = base + w * 2;
        rp[it] += 2 * (w & 3) + (w >> 2);
    }

    float acc[2][6][4];
#pragma unroll
    for (int mt = 0; mt < 2; mt++)
#pragma unroll
        for (int i = 0; i < 6; i++)
#pragma unroll
            for (int j = 0; j < 4; j++) acc[mt][i][j] = 0.f;

    float2 pf[8];
#pragma unroll
    for (int it = 0; it < 8; it++) pf[it] = *(const float2*)srcs[it];
#pragma unroll
    for (int it = 0; it < 8; it++) {
        const float a = pf[it].x, b = pf[it].y;
        __nv_bfloat162 h2 = __floats2bfloat162_rn(a, b);
        const uint32_t hu = *(const uint32_t*)&h2;
        const float ha = __uint_as_float(hu << 16);
        const float hb = __uint_as_float(hu & 0xFFFF0000u);
        __nv_bfloat162 l2 = __floats2bfloat162_rn(a - ha, b - hb);
        ((uint32_t*)sm_h[0])[rp[it]] = hu;
        ((uint32_t*)sm_l[0])[rp[it]] = *(const uint32_t*)&l2;
    }

    for (int c = 0; c < NCHUNK; c++) {
        __syncthreads();
        const int cur = c & 1;
        const bool more = (c + 1 < NCHUNK);

        if (more) {
            const int koff = (c + 1) * KC;
#pragma unroll
            for (int it = 0; it < 8; it++)
                pf[it] = *(const float2*)(srcs[it] + koff);
        }

        uint32_t ah[2][4], al[2][4];
#pragma unroll
        for (int mt = 0; mt < 2; mt++) {
            const int mrow = mh * 32 + mt * 16 + grp;
            uint2 q0 = *(const uint2*)&sm_h[cur][mrow][tig * 2];
            uint2 q1 = *(const uint2*)&sm_h[cur][mrow + 8][tig * 2];
            ah[mt][0] = q0.x; ah[mt][2] = q0.y;
            ah[mt][1] = q1.x; ah[mt][3] = q1.y;
            uint2 s0 = *(const uint2*)&sm_l[cur][mrow][tig * 2];
            uint2 s1 = *(const uint2*)&sm_l[cur][mrow + 8][tig * 2];
            al[mt][0] = s0.x; al[mt][2] = s0.y;
            al[mt][1] = s1.x; al[mt][3] = s1.y;
        }

#pragma unroll
        for (int i = 0; i < 6; i++) {
            const int wrow = 64 + (nq * 6 + i) * 8 + grp;
            uint2 bh2 = *(const uint2*)&sm_h[cur][wrow][tig * 2];
            uint2 bl2 = *(const uint2*)&sm_l[cur][wrow][tig * 2];
            uint32_t bh[2] = {bh2.x, bh2.y};
            uint32_t bl[2] = {bl2.x, bl2.y};
#pragma unroll
            for (int mt = 0; mt < 2; mt++) {
                mma_bf16(acc[mt][i], al[mt], bh);
                mma_bf16(acc[mt][i], ah[mt], bl);
                mma_bf16(acc[mt][i], ah[mt], bh);
            }
        }

        if (more) {
            const int nxt = cur ^ 1;
#pragma unroll
            for (int it = 0; it < 8; it++) {
                const float a = pf[it].x, b = pf[it].y;
                __nv_bfloat162 h2 = __floats2bfloat162_rn(a, b);
                const uint32_t hu = *(const uint32_t*)&h2;
                const float ha = __uint_as_float(hu << 16);
                const float hb = __uint_as_float(hu & 0xFFFF0000u);
                __nv_bfloat162 l2 = __floats2bfloat162_rn(a - ha, b - hb);
                ((uint32_t*)sm_h[nxt])[rp[it]] = hu;
                ((uint32_t*)sm_l[nxt])[rp[it]] = *(const uint32_t*)&l2;
            }
        }
    }

#pragma unroll
    for (int mt = 0; mt < 2; mt++) {
        const int mwr = m0 + mh * 32 + mt * 16 + grp;
#pragma unroll
        for (int i = 0; i < 6; i++) {
            const int ntg = nq * 6 + i;
            float* out = (ntg < 8) ? g_Q : (ntg < 16) ? g_K : g_V;
            const int col = (ntg & 7) * 8 + tig * 2;
            *(float2*)&out[(size_t)mwr * H_SZ + col] =
                make_float2(acc[mt][i][0], acc[mt][i][1]);
            *(float2*)&out[(size_t)(mwr + 8) * H_SZ + col] =
                make_float2(acc[mt][i][2], acc[mt][i][3]);
        }
    }
}

// ---------------------------------------------------------------------------
// Sparse BigBird attention, 4 query rows per block, SOFTWARE-PIPELINED:
// score loop prefetches next iteration's K tile (clamped index, warp-uniform
// guard keeps shuffles convergent); V loop prefetches next (weights, V) pair.
// ---------------------------------------------------------------------------
#define QR 4
#define MAXC 392

__global__ __launch_bounds__(256, 4) void attn4_kernel(
    const int* __restrict__ random_cols,
    float* __restrict__ out)
{
    const int blk = blockIdx.x;            // 0 .. 4095
    const int b   = blk >> 9;              // 512 blocks per batch
    const int r0  = (blk & 511) * QR;
    const int r3  = r0 + 3;

    __shared__ int   cols[MAXC];
    __shared__ __align__(16) float sc[MAXC][4];
    __shared__ __align__(16) float qs[QR][H_SZ];
    __shared__ uint32_t rbit[QR][64];
    __shared__ uint32_t ubit[64];
    __shared__ int   s_n;
    __shared__ __align__(16) float4 red4[8];
    __shared__ float4 s_mx4, s_inv4;
    __shared__ __align__(16) float outp[16][256];   // [group][row*64+dim]

    const int tid  = threadIdx.x;
    const int lane = tid & 31;
    const int warp = tid >> 5;
    const int i4   = tid >> 6;    // 0..3  (row for setup)
    const int j4   = tid & 63;    // 0..63

    // ---- phase 0: init + loads ----
    rbit[i4][j4] = 0;
    if (tid < 64) ubit[tid] = 0;
    if (tid == 0) s_n = 0;
    const int myrnd = random_cols[(r0 + i4) * NRAND + j4];
    qs[i4][j4] = g_Q[((size_t)b * T_SZ + r0 + i4) * H_SZ + j4];

    const int lo0 = max(0, r0 - (WIN - 1));
    const int gn  = min(NGLOB, r3 + 1);
    const int l0u = max(64, lo0);
    const int ln  = max(0, r3 - l0u + 1);
    __syncthreads();

    // ---- phase 1: bitmaps + union list ----
    atomicOr(&rbit[i4][myrnd >> 5], 1u << (myrnd & 31));
    if (tid < gn) cols[tid] = tid;
    if (tid >= 64 && tid < 64 + ln) cols[gn + tid - 64] = l0u + (tid - 64);
    if (myrnd >= 64 && myrnd < lo0) {
        uint32_t bit = 1u << (myrnd & 31);
        uint32_t old = atomicOr(&ubit[myrnd >> 5], bit);
        if (!(old & bit)) {
            int p = atomicAdd(&s_n, 1);
            cols[gn + ln + p] = myrnd;
        }
    }
    __syncthreads();
    const int n = gn + ln + s_n;

    // ---- score pass: 8-lane groups, prefetch-pipelined ----
    const int l8 = lane & 7;
    const int g8 = lane >> 3;
    float4 qA[QR], qB[QR];
#pragma unroll
    for (int i = 0; i < QR; i++) {
        qA[i] = *(const float4*)&qs[i][l8 * 8];
        qB[i] = *(const float4*)&qs[i][l8 * 8 + 4];
    }
    const size_t bbase = (size_t)b * T_SZ;

    // prefetch iteration 0
    float4 ka, kb;
    {
        const int cc = cols[min(warp * 4 + g8, n - 1)];
        const float* kp = &g_K[(bbase + cc) * H_SZ + l8 * 8];
        ka = *(const float4*)kp;
        kb = *(const float4*)(kp + 4);
    }

    for (int ci0 = warp * 4; ci0 < n; ci0 += 32) {     // warp-uniform bound
        const int  ci  = ci0 + g8;
        const bool act = (ci < n);
        const float4 kA = ka, kB = kb;

        // prefetch next iteration's K (warp-uniform guard, clamped index)
        if (ci0 + 32 < n) {
            const int cc = cols[min(ci0 + 32 + g8, n - 1)];
            const float* kp = &g_K[(bbase + cc) * H_SZ + l8 * 8];
            ka = *(const float4*)kp;
            kb = *(const float4*)(kp + 4);
        }

        float p0 = qA[0].x*kA.x + qA[0].y*kA.y + qA[0].z*kA.z + qA[0].w*kA.w
                 + qB[0].x*kB.x + qB[0].y*kB.y + qB[0].z*kB.z + qB[0].w*kB.w;
        float p1 = qA[1].x*kA.x + qA[1].y*kA.y + qA[1].z*kA.z + qA[1].w*kA.w
                 + qB[1].x*kB.x + qB[1].y*kB.y + qB[1].z*kB.z + qB[1].w*kB.w;
        float p2 = qA[2].x*kA.x + qA[2].y*kA.y + qA[2].z*kA.z + qA[2].w*kA.w
                 + qB[2].x*kB.x + qB[2].y*kB.y + qB[2].z*kB.z + qB[2].w*kB.w;
        float p3 = qA[3].x*kA.x + qA[3].y*kA.y + qA[3].z*kA.z + qA[3].w*kA.w
                 + qB[3].x*kB.x + qB[3].y*kB.y + qB[3].z*kB.z + qB[3].w*kB.w;
#pragma unroll
        for (int o = 4; o; o >>= 1) {
            p0 += __shfl_xor_sync(0xffffffffu, p0, o);
            p1 += __shfl_xor_sync(0xffffffffu, p1, o);
            p2 += __shfl_xor_sync(0xffffffffu, p2, o);
            p3 += __shfl_xor_sync(0xffffffffu, p3, o);
        }
        if (act && l8 < QR) {
            const int ri = r0 + l8;
            const int c  = cols[ci];
            float pv = (l8 == 0) ? p0 : (l8 == 1) ? p1 : (l8 == 2) ? p2 : p3;
            bool allowed = (c <= ri) &&
                           ((c > ri - WIN) || (c < NGLOB) ||
                            ((rbit[l8][c >> 5] >> (c & 31)) & 1u));
            sc[ci][l8] = allowed ? pv * 0.125f : -INFINITY;
        }
    }
    __syncthreads();

    // ---- softmax pass 1: componentwise max over 4 rows ----
    float4 m4 = make_float4(-1e30f, -1e30f, -1e30f, -1e30f);
    for (int ci = tid; ci < n; ci += 256) {
        float4 s4 = *(const float4*)&sc[ci][0];
        m4.x = fmaxf(m4.x, s4.x); m4.y = fmaxf(m4.y, s4.y);
        m4.z = fmaxf(m4.z, s4.z); m4.w = fmaxf(m4.w, s4.w);
    }
#pragma unroll
    for (int o = 16; o; o >>= 1) {
        m4.x = fmaxf(m4.x, __shfl_xor_sync(0xffffffffu, m4.x, o));
        m4.y = fmaxf(m4.y, __shfl_xor_sync(0xffffffffu, m4.y, o));
        m4.z = fmaxf(m4.z, __shfl_xor_sync(0xffffffffu, m4.z, o));
        m4.w = fmaxf(m4.w, __shfl_xor_sync(0xffffffffu, m4.w, o));
    }
    if (lane == 0) red4[warp] = m4;
    __syncthreads();
    if (tid == 0) {
        float4 m = red4[0];
#pragma unroll
        for (int w = 1; w < 8; w++) {
            m.x = fmaxf(m.x, red4[w].x); m.y = fmaxf(m.y, red4[w].y);
            m.z = fmaxf(m.z, red4[w].z); m.w = fmaxf(m.w, red4[w].w);
        }
        s_mx4 = m;
    }
    __syncthreads();
    const float4 mx = s_mx4;

    // ---- softmax pass 2: exp + sum ----
    float4 sum4 = make_float4(0.f, 0.f, 0.f, 0.f);
    for (int ci = tid; ci < n; ci += 256) {
        float4 s4 = *(const float4*)&sc[ci][0];
        s4.x = __expf(s4.x - mx.x); s4.y = __expf(s4.y - mx.y);
        s4.z = __expf(s4.z - mx.z); s4.w = __expf(s4.w - mx.w);
        *(float4*)&sc[ci][0] = s4;
        sum4.x += s4.x; sum4.y += s4.y; sum4.z += s4.z; sum4.w += s4.w;
    }
#pragma unroll
    for (int o = 16; o; o >>= 1) {
        sum4.x += __shfl_xor_sync(0xffffffffu, sum4.x, o);
        sum4.y += __shfl_xor_sync(0xffffffffu, sum4.y, o);
        sum4.z += __shfl_xor_sync(0xffffffffu, sum4.z, o);
        sum4.w += __shfl_xor_sync(0xffffffffu, sum4.w, o);
    }
    if (lane == 0) red4[warp] = sum4;
    __syncthreads();
    if (tid == 0) {
        float4 s = red4[0];
#pragma unroll
        for (int w = 1; w < 8; w++) {
            s.x += red4[w].x; s.y += red4[w].y;
            s.z += red4[w].z; s.w += red4[w].w;
        }
        s_inv4 = make_float4(1.f/s.x, 1.f/s.y, 1.f/s.z, 1.f/s.w);
    }
    __syncthreads();

    // ---- V pass: 16 groups of 16 threads, prefetch-pipelined ----
    const int dg = tid & 15;
    const int gq = tid >> 4;
    float4 a0 = make_float4(0,0,0,0), a1 = a0, a2 = a0, a3 = a0;

    float4 wn, vn;
    if (gq < n) {
        wn = *(const float4*)&sc[gq][0];
        vn = *(const float4*)&g_V[(bbase + cols[gq]) * H_SZ + dg * 4];
    }
    for (int ci = gq; ci < n; ci += 16) {
        const float4 w4 = wn, v = vn;
        if (ci + 16 < n) {
            wn = *(const float4*)&sc[ci + 16][0];
            vn = *(const float4*)&g_V[(bbase + cols[ci + 16]) * H_SZ + dg * 4];
        }
        a0.x += w4.x*v.x; a0.y += w4.x*v.y; a0.z += w4.x*v.z; a0.w += w4.x*v.w;
        a1.x += w4.y*v.x; a1.y += w4.y*v.y; a1.z += w4.y*v.z; a1.w += w4.y*v.w;
        a2.x += w4.z*v.x; a2.y += w4.z*v.y; a2.z += w4.z*v.z; a2.w += w4.z*v.w;
        a3.x += w4.w*v.x; a3.y += w4.w*v.y; a3.z += w4.w*v.z; a3.w += w4.w*v.w;
    }
    *(float4*)&outp[gq][0 * 64 + dg * 4] = a0;
    *(float4*)&outp[gq][1 * 64 + dg * 4] = a1;
    *(float4*)&outp[gq][2 * 64 + dg * 4] = a2;
    *(float4*)&outp[gq][3 * 64 + dg * 4] = a3;
    __syncthreads();

    // ---- final reduce + normalize ----
    {
        const int i = tid >> 6;
        const int d = tid & 63;
        float o = 0.f;
#pragma unroll
        for (int g2 = 0; g2 < 16; g2++) o += outp[g2][i * 64 + d];
        float inv = (i == 0) ? s_inv4.x : (i == 1) ? s_inv4.y
                  : (i == 2) ? s_inv4.z : s_inv4.w;
        out[((size_t)b * T_SZ + r0 + i) * H_SZ + d] = o * inv;
    }
}

// ---------------------------------------------------------------------------
// kernel_launch — inputs per metadata order: x, random_cols, Wk, Wq, Wv
// ---------------------------------------------------------------------------
extern "C" void kernel_launch(void* const* d_in, const int* in_sizes, int n_in,
                              void* d_out, int out_size)
{
    const float* x           = (const float*)d_in[0];
    const int*   random_cols = (const int*)  d_in[1];
    const float* Wk          = (const float*)d_in[2];
    const float* Wq          = (const float*)d_in[3];
    const float* Wv          = (const float*)d_in[4];
    float* out = (float*)d_out;

    proj_tc_kernel<<<BT / 64, 256>>>(x, Wq, Wk, Wv);

    attn4_kernel<<<BT / QR, 256>>>(random_cols, out);
}

// round 11
// speedup vs baseline: 1.0106x; 1.0106x over previous
#include <cuda_runtime.h>
#include <cuda_bf16.h>
#include <math.h>
#include <stdint.h>

#define B_SZ 8
#define T_SZ 2048
#define C_SZ 1024
#define H_SZ 64
#define WIN 64
#define NGLOB 64
#define NRAND 64
#define BT (B_SZ * T_SZ)

// Scratch: Q fp32; K,V pre-split bf16 hi/lo (bf16x2 words, 32 per token).
__device__ float    g_Q [BT * H_SZ];
__device__ uint32_t g_Kh[BT * 32];
__device__ uint32_t g_Kl[BT * 32];
__device__ uint32_t g_Vh[BT * 32];
__device__ uint32_t g_Vl[BT * 32];

__device__ __forceinline__ void mma_bf16(float* c, const uint32_t* a, const uint32_t* b) {
    asm volatile(
        "mma.sync.aligned.m16n8k16.row.col.f32.bf16.bf16.f32 "
        "{%0,%1,%2,%3}, {%4,%5,%6,%7}, {%8,%9}, {%0,%1,%2,%3};"
        : "+f"(c[0]), "+f"(c[1]), "+f"(c[2]), "+f"(c[3])
        : "r"(a[0]), "r"(a[1]), "r"(a[2]), "r"(a[3]), "r"(b[0]), "r"(b[1]));
}

__device__ __forceinline__ void ldmx2t(uint32_t& r0, uint32_t& r1, uint32_t addr) {
    asm volatile("ldmatrix.sync.aligned.m8n8.x2.trans.shared.b16 {%0,%1}, [%2];"
                 : "=r"(r0), "=r"(r1) : "r"(addr));
}

__device__ __forceinline__ void split2(float a, float b, uint32_t& hw, uint32_t& lw) {
    __nv_bfloat162 h2 = __floats2bfloat162_rn(a, b);
    hw = *(uint32_t*)&h2;
    float ra = a - __uint_as_float(hw << 16);
    float rb = b - __uint_as_float(hw & 0xFFFF0000u);
    __nv_bfloat162 l2 = __floats2bfloat162_rn(ra, rb);
    lw = *(uint32_t*)&l2;
}

// ---------------------------------------------------------------------------
// FUSED projection GEMM (Q,K,V), bf16 3-split, ping-pong smem (verified).
// Epilogue: Q fp32; K,V written as split bf16 hi/lo words.
// ---------------------------------------------------------------------------
#define KC 16
#define PADK 12
#define NCHUNK (C_SZ / KC)

__global__ __launch_bounds__(256, 2) void proj_tc_kernel(
    const float* __restrict__ x, const float* __restrict__ Wq,
    const float* __restrict__ Wk, const float* __restrict__ Wv)
{
    __shared__ __align__(16) uint32_t sm_h[2][256][PADK];
    __shared__ __align__(16) uint32_t sm_l[2][256][PADK];

    const int m0 = blockIdx.x * 64;
    const int tid = threadIdx.x, warp = tid >> 5, lane = tid & 31;
    const int grp = lane >> 2, tig = lane & 3;
    const int mh = warp & 1, nq = warp >> 1;

    const float* srcs[8];
    int rp[8];
#pragma unroll
    for (int it = 0; it < 8; it++) {
        const int i = it * 256 + tid;
        int r, w; const float* base;
        if (it < 2) {
            r = i >> 3; w = i & 7;
            base = &x[(size_t)(m0 + r) * C_SZ];
            rp[it] = r * PADK;
        } else {
            const int j = i - 512;
            r = j >> 3; w = j & 7;
            base = (r < 64) ? &Wq[(size_t)r * C_SZ]
                 : (r < 128) ? &Wk[(size_t)(r - 64) * C_SZ]
                             : &Wv[(size_t)(r - 128) * C_SZ];
            rp[it] = (64 + r) * PADK;
        }
        srcs[it] = base + w * 2;
        rp[it] += 2 * (w & 3) + (w >> 2);
    }

    float acc[2][6][4];
#pragma unroll
    for (int mt = 0; mt < 2; mt++)
#pragma unroll
        for (int i = 0; i < 6; i++)
#pragma unroll
            for (int j = 0; j < 4; j++) acc[mt][i][j] = 0.f;

    float2 pf[8];
#pragma unroll
    for (int it = 0; it < 8; it++) pf[it] = *(const float2*)srcs[it];
#pragma unroll
    for (int it = 0; it < 8; it++) {
        uint32_t hu, lu;
        split2(pf[it].x, pf[it].y, hu, lu);
        ((uint32_t*)sm_h[0])[rp[it]] = hu;
        ((uint32_t*)sm_l[0])[rp[it]] = lu;
    }

    for (int c = 0; c < NCHUNK; c++) {
        __syncthreads();
        const int cur = c & 1;
        const bool more = (c + 1 < NCHUNK);
        if (more) {
            const int koff = (c + 1) * KC;
#pragma unroll
            for (int it = 0; it < 8; it++) pf[it] = *(const float2*)(srcs[it] + koff);
        }
        uint32_t ah[2][4], al[2][4];
#pragma unroll
        for (int mt = 0; mt < 2; mt++) {
            const int mrow = mh * 32 + mt * 16 + grp;
            uint2 q0 = *(const uint2*)&sm_h[cur][mrow][tig * 2];
            uint2 q1 = *(const uint2*)&sm_h[cur][mrow + 8][tig * 2];
            ah[mt][0] = q0.x; ah[mt][2] = q0.y; ah[mt][1] = q1.x; ah[mt][3] = q1.y;
            uint2 s0 = *(const uint2*)&sm_l[cur][mrow][tig * 2];
            uint2 s1 = *(const uint2*)&sm_l[cur][mrow + 8][tig * 2];
            al[mt][0] = s0.x; al[mt][2] = s0.y; al[mt][1] = s1.x; al[mt][3] = s1.y;
        }
#pragma unroll
        for (int i = 0; i < 6; i++) {
            const int wrow = 64 + (nq * 6 + i) * 8 + grp;
            uint2 bh2 = *(const uint2*)&sm_h[cur][wrow][tig * 2];
            uint2 bl2 = *(const uint2*)&sm_l[cur][wrow][tig * 2];
            uint32_t bh[2] = {bh2.x, bh2.y};
            uint32_t bl[2] = {bl2.x, bl2.y};
#pragma unroll
            for (int mt = 0; mt < 2; mt++) {
                mma_bf16(acc[mt][i], al[mt], bh);
                mma_bf16(acc[mt][i], ah[mt], bl);
                mma_bf16(acc[mt][i], ah[mt], bh);
            }
        }
        if (more) {
            const int nxt = cur ^ 1;
#pragma unroll
            for (int it = 0; it < 8; it++) {
                uint32_t hu, lu;
                split2(pf[it].x, pf[it].y, hu, lu);
                ((uint32_t*)sm_h[nxt])[rp[it]] = hu;
                ((uint32_t*)sm_l[nxt])[rp[it]] = lu;
            }
        }
    }

#pragma unroll
    for (int mt = 0; mt < 2; mt++) {
        const int mwr = m0 + mh * 32 + mt * 16 + grp;
#pragma unroll
        for (int i = 0; i < 6; i++) {
            const int ntg = nq * 6 + i;
            const float a0 = acc[mt][i][0], a1 = acc[mt][i][1];
            const float a2 = acc[mt][i][2], a3 = acc[mt][i][3];
            if (ntg < 8) {
                const int col = ntg * 8 + tig * 2;
                *(float2*)&g_Q[(size_t)mwr * H_SZ + col]       = make_float2(a0, a1);
                *(float2*)&g_Q[(size_t)(mwr + 8) * H_SZ + col] = make_float2(a2, a3);
            } else {
                uint32_t* dh = (ntg < 16) ? g_Kh : g_Vh;
                uint32_t* dl = (ntg < 16) ? g_Kl : g_Vl;
                const int word = (ntg & 7) * 4 + tig;   // col/2
                uint32_t hu, lu;
                split2(a0, a1, hu, lu);
                dh[(size_t)mwr * 32 + word] = hu;
                dl[(size_t)mwr * 32 + word] = lu;
                split2(a2, a3, hu, lu);
                dh[(size_t)(mwr + 8) * 32 + word] = hu;
                dl[(size_t)(mwr + 8) * 32 + word] = lu;
            }
        }
    }
}

// ---------------------------------------------------------------------------
// Flash-style sparse BigBird attention on tensor cores. 16 rows/block.
// Fixed-shift softmax exp(s-12): exactly shift-invariant, no running max.
// QK: warp w -> cols 8w..8w+7 (C: rows grp/grp+8, cols 2tig/2tig+1).
// PV: warp w -> dims 8w..8w+7; P via smem (pair-permuted, LDS.64 A-frags);
// V B-frags via ldmatrix.x2.trans.b16 from natural [col][dim] tiles.
// ---------------------------------------------------------------------------
#define QR 16
#define MAXC 1184
#define KST 36
#define SHIFT 12.0f

__global__ __launch_bounds__(256) void attn16_kernel(
    const int* __restrict__ random_cols, float* __restrict__ out)
{
    __shared__ __align__(16) uint32_t kh[64][KST], kl[64][KST];
    __shared__ __align__(16) uint32_t vh[64][KST], vl[64][KST];
    __shared__ __align__(16) uint32_t pool[2 * 16 * KST];   // qs then ph|pl
    __shared__ uint16_t cols[MAXC];
    __shared__ uint32_t rbit[QR][64];
    __shared__ uint32_t ubit[64];
    __shared__ float lred[8][16];
    __shared__ int s_n;

    float* qs = (float*)pool;
    uint32_t (*ph)[KST] = (uint32_t(*)[KST])pool;
    uint32_t (*pl)[KST] = (uint32_t(*)[KST])(pool + 16 * KST);

    const int blk = blockIdx.x;            // 0..1023
    const int b   = blk >> 7;
    const int r0  = (blk & 127) * QR;
    const int r3  = r0 + QR - 1;
    const int tid = threadIdx.x, wid = tid >> 5, lane = tid & 31;
    const int grp = lane >> 2, tig = lane & 3;
    const size_t bbase = (size_t)b * T_SZ;

    const int lo0 = max(0, r0 - (WIN - 1));
    const int gn  = min(NGLOB, r3 + 1);
    const int l0u = max(64, lo0);
    const int ln  = max(0, r3 - l0u + 1);

    // phase A: load scaled Q, zero bitmaps
    for (int i = tid; i < QR * 64; i += 256) {
        qs[i] = g_Q[(bbase + r0 + (i >> 6)) * H_SZ + (i & 63)] * 0.125f;
        rbit[i >> 6][i & 63] = 0;
    }
    if (tid < 64) ubit[tid] = 0;
    if (tid == 0) s_n = 0;
    __syncthreads();

    // phase B1: Q fragments (bf16 3-split), rows grp & grp+8
    uint32_t aqh[4][4], aql[4][4];
#pragma unroll
    for (int ks = 0; ks < 4; ks++) {
        const float* qA = qs + grp * 64 + ks * 16 + 2 * tig;
        const float* qB = qs + (grp + 8) * 64 + ks * 16 + 2 * tig;
        split2(qA[0], qA[1], aqh[ks][0], aql[ks][0]);
        split2(qB[0], qB[1], aqh[ks][1], aql[ks][1]);
        split2(qA[8], qA[9], aqh[ks][2], aql[ks][2]);
        split2(qB[8], qB[9], aqh[ks][3], aql[ks][3]);
    }

    // phase B2: union column list + random bitmaps
    if (tid < gn) cols[tid] = (uint16_t)tid;
    if (tid >= 64 && tid < 64 + ln) cols[gn + tid - 64] = (uint16_t)(l0u + tid - 64);
    for (int i = tid; i < QR * NRAND; i += 256) {
        const int row = i >> 6;
        const int v = random_cols[(r0 + row) * NRAND + (i & 63)];
        atomicOr(&rbit[row][v >> 5], 1u << (v & 31));
        if (v >= 64 && v < l0u) {
            const uint32_t bit = 1u << (v & 31);
            if (!(atomicOr(&ubit[v >> 5], bit) & bit))
                cols[gn + ln + atomicAdd(&s_n, 1)] = (uint16_t)v;
        }
    }
    __syncthreads();
    const int n = gn + ln + s_n;
    const int ntiles = (n + 63) >> 6;

    float oc[4] = {0.f, 0.f, 0.f, 0.f};
    float lA = 0.f, lB = 0.f;

    for (int t = 0; t < ntiles; t++) {
        __syncthreads();                         // tile buffers + P pool free
        const int tile0 = t << 6;

        // gather K,V (pre-split bf16, straight copies)
        for (int e = tid; e < 512; e += 256) {
            const int lc = e >> 3, ch = (e & 7) << 2;
            const int idx = tile0 + lc;
            const int cg = (idx < n) ? (int)cols[idx] : 0;
            const size_t gb = (bbase + cg) * 32 + ch;
            *(uint4*)&kh[lc][ch] = *(const uint4*)&g_Kh[gb];
            *(uint4*)&kl[lc][ch] = *(const uint4*)&g_Kl[gb];
            *(uint4*)&vh[lc][ch] = *(const uint4*)&g_Vh[gb];
            *(uint4*)&vl[lc][ch] = *(const uint4*)&g_Vl[gb];
        }
        __syncthreads();

        // QK
        float sc[4] = {0.f, 0.f, 0.f, 0.f};
        const int kr = (wid << 3) + grp;
#pragma unroll
        for (int ks = 0; ks < 4; ks++) {
            uint32_t bh[2] = { kh[kr][(ks << 3) + tig], kh[kr][(ks << 3) + tig + 4] };
            uint32_t bl[2] = { kl[kr][(ks << 3) + tig], kl[kr][(ks << 3) + tig + 4] };
            mma_bf16(sc, aql[ks], bh);
            mma_bf16(sc, aqh[ks], bl);
            mma_bf16(sc, aqh[ks], bh);
        }

        // mask + exp (fixed shift) + row-sum partials
        const int iA = tile0 + (wid << 3) + (tig << 1);
        const int cA = (iA < n) ? (int)cols[iA] : -1;
        const int cB = (iA + 1 < n) ? (int)cols[iA + 1] : -1;
        const int rA = r0 + grp, rB = rA + 8;
#define OKM(r, c, rl) ((c) >= 0 && (c) <= (r) && ((c) > (r) - WIN || (c) < NGLOB || \
                       ((rbit[rl][(c) >> 5] >> ((c) & 31)) & 1u)))
        const float p00 = OKM(rA, cA, grp)     ? __expf(sc[0] - SHIFT) : 0.f;
        const float p01 = OKM(rA, cB, grp)     ? __expf(sc[1] - SHIFT) : 0.f;
        const float p10 = OKM(rB, cA, grp + 8) ? __expf(sc[2] - SHIFT) : 0.f;
        const float p11 = OKM(rB, cB, grp + 8) ? __expf(sc[3] - SHIFT) : 0.f;
#undef OKM
        lA += p00 + p01;
        lB += p10 + p11;

        // store P (split, pair-permuted word position)
        {
            const int w = (wid << 2) + tig;
            const int pp = ((w >> 3) << 3) + ((w & 3) << 1) + ((w >> 2) & 1);
            uint32_t hw, lw;
            split2(p00, p01, hw, lw);
            ph[grp][pp] = hw; pl[grp][pp] = lw;
            split2(p10, p11, hw, lw);
            ph[grp + 8][pp] = hw; pl[grp + 8][pp] = lw;
        }
        __syncthreads();

        // PV
#pragma unroll
        for (int ks = 0; ks < 4; ks++) {
            uint32_t pah[4], pal[4];
            uint2 t0 = *(const uint2*)&ph[grp][(ks << 3) + (tig << 1)];
            uint2 t1 = *(const uint2*)&ph[grp + 8][(ks << 3) + (tig << 1)];
            pah[0] = t0.x; pah[2] = t0.y; pah[1] = t1.x; pah[3] = t1.y;
            uint2 t2 = *(const uint2*)&pl[grp][(ks << 3) + (tig << 1)];
            uint2 t3 = *(const uint2*)&pl[grp + 8][(ks << 3) + (tig << 1)];
            pal[0] = t2.x; pal[2] = t2.y; pal[1] = t3.x; pal[3] = t3.y;

            const int vrow = (ks << 4) + (lane & 15);
            uint32_t bvh[2], bvl[2];
            ldmx2t(bvh[0], bvh[1],
                   (uint32_t)__cvta_generic_to_shared(&vh[vrow][wid << 2]));
            ldmx2t(bvl[0], bvl[1],
                   (uint32_t)__cvta_generic_to_shared(&vl[vrow][wid << 2]));
            mma_bf16(oc, pal, bvh);
            mma_bf16(oc, pah, bvl);
            mma_bf16(oc, pah, bvh);
        }
    }

    // reduce row sums over tig lanes, then over warps
    lA += __shfl_xor_sync(0xffffffffu, lA, 1);
    lA += __shfl_xor_sync(0xffffffffu, lA, 2);
    lB += __shfl_xor_sync(0xffffffffu, lB, 1);
    lB += __shfl_xor_sync(0xffffffffu, lB, 2);
    if (tig == 0) { lred[wid][grp] = lA; lred[wid][grp + 8] = lB; }
    __syncthreads();

    float sA = 0.f, sB = 0.f;
#pragma unroll
    for (int w2 = 0; w2 < 8; w2++) { sA += lred[w2][grp]; sB += lred[w2][grp + 8]; }

    const int dim = (wid << 3) + (tig << 1);
    const float iA2 = 1.f / sA, iB2 = 1.f / sB;
    *(float2*)&out[(bbase + r0 + grp) * H_SZ + dim] =
        make_float2(oc[0] * iA2, oc[1] * iA2);
    *(float2*)&out[(bbase + r0 + grp + 8) * H_SZ + dim] =
        make_float2(oc[2] * iB2, oc[3] * iB2);
}

// ---------------------------------------------------------------------------
// kernel_launch — inputs per metadata order: x, random_cols, Wk, Wq, Wv
// ---------------------------------------------------------------------------
extern "C" void kernel_launch(void* const* d_in, const int* in_sizes, int n_in,
                              void* d_out, int out_size)
{
    const float* x           = (const float*)d_in[0];
    const int*   random_cols = (const int*)  d_in[1];
    const float* Wk          = (const float*)d_in[2];
    const float* Wq          = (const float*)d_in[3];
    const float* Wv          = (const float*)d_in[4];
    float* out = (float*)d_out;

    proj_tc_kernel<<<BT / 64, 256>>>(x, Wq, Wk, Wv);
    attn16_kernel<<<BT / QR, 256>>>(random_cols, out);
}

// round 12
// speedup vs baseline: 1.0278x; 1.0171x over previous
#include <cuda_runtime.h>
#include <cuda_bf16.h>
#include <math.h>
#include <stdint.h>

#define B_SZ 8
#define T_SZ 2048
#define C_SZ 1024
#define H_SZ 64
#define WIN 64
#define NGLOB 64
#define NRAND 64
#define BT (B_SZ * T_SZ)

// Scratch: Q fp32; K,V pre-split bf16 hi/lo (bf16x2 words, 32 per token).
__device__ float    g_Q [BT * H_SZ];
__device__ uint32_t g_Kh[BT * 32];
__device__ uint32_t g_Kl[BT * 32];
__device__ uint32_t g_Vh[BT * 32];
__device__ uint32_t g_Vl[BT * 32];

__device__ __forceinline__ void mma_bf16(float* c, const uint32_t* a, const uint32_t* b) {
    asm volatile(
        "mma.sync.aligned.m16n8k16.row.col.f32.bf16.bf16.f32 "
        "{%0,%1,%2,%3}, {%4,%5,%6,%7}, {%8,%9}, {%0,%1,%2,%3};"
        : "+f"(c[0]), "+f"(c[1]), "+f"(c[2]), "+f"(c[3])
        : "r"(a[0]), "r"(a[1]), "r"(a[2]), "r"(a[3]), "r"(b[0]), "r"(b[1]));
}

__device__ __forceinline__ void ldmx2t(uint32_t& r0, uint32_t& r1, uint32_t addr) {
    asm volatile("ldmatrix.sync.aligned.m8n8.x2.trans.shared.b16 {%0,%1}, [%2];"
                 : "=r"(r0), "=r"(r1) : "r"(addr));
}

__device__ __forceinline__ void split2(float a, float b, uint32_t& hw, uint32_t& lw) {
    __nv_bfloat162 h2 = __floats2bfloat162_rn(a, b);
    hw = *(uint32_t*)&h2;
    float ra = a - __uint_as_float(hw << 16);
    float rb = b - __uint_as_float(hw & 0xFFFF0000u);
    __nv_bfloat162 l2 = __floats2bfloat162_rn(ra, rb);
    lw = *(uint32_t*)&l2;
}

__device__ __forceinline__ void cp16(void* smem_dst, const void* gsrc) {
    uint32_t sa = (uint32_t)__cvta_generic_to_shared(smem_dst);
    asm volatile("cp.async.cg.shared.global [%0], [%1], 16;" :: "r"(sa), "l"(gsrc));
}

// ---------------------------------------------------------------------------
// FUSED projection GEMM (Q,K,V), bf16 3-split, ping-pong smem (verified).
// Epilogue: Q fp32; K,V written as split bf16 hi/lo words.
// ---------------------------------------------------------------------------
#define KC 16
#define PADK 12
#define NCHUNK (C_SZ / KC)

__global__ __launch_bounds__(256, 2) void proj_tc_kernel(
    const float* __restrict__ x, const float* __restrict__ Wq,
    const float* __restrict__ Wk, const float* __restrict__ Wv)
{
    __shared__ __align__(16) uint32_t sm_h[2][256][PADK];
    __shared__ __align__(16) uint32_t sm_l[2][256][PADK];

    const int m0 = blockIdx.x * 64;
    const int tid = threadIdx.x, warp = tid >> 5, lane = tid & 31;
    const int grp = lane >> 2, tig = lane & 3;
    const int mh = warp & 1, nq = warp >> 1;

    const float* srcs[8];
    int rp[8];
#pragma unroll
    for (int it = 0; it < 8; it++) {
        const int i = it * 256 + tid;
        int r, w; const float* base;
        if (it < 2) {
            r = i >> 3; w = i & 7;
            base = &x[(size_t)(m0 + r) * C_SZ];
            rp[it] = r * PADK;
        } else {
            const int j = i - 512;
            r = j >> 3; w = j & 7;
            base = (r < 64) ? &Wq[(size_t)r * C_SZ]
                 : (r < 128) ? &Wk[(size_t)(r - 64) * C_SZ]
                             : &Wv[(size_t)(r - 128) * C_SZ];
            rp[it] = (64 + r) * PADK;
        }
        srcs[it] = base + w * 2;
        rp[it] += 2 * (w & 3) + (w >> 2);
    }

    float acc[2][6][4];
#pragma unroll
    for (int mt = 0; mt < 2; mt++)
#pragma unroll
        for (int i = 0; i < 6; i++)
#pragma unroll
            for (int j = 0; j < 4; j++) acc[mt][i][j] = 0.f;

    float2 pf[8];
#pragma unroll
    for (int it = 0; it < 8; it++) pf[it] = *(const float2*)srcs[it];
#pragma unroll
    for (int it = 0; it < 8; it++) {
        uint32_t hu, lu;
        split2(pf[it].x, pf[it].y, hu, lu);
        ((uint32_t*)sm_h[0])[rp[it]] = hu;
        ((uint32_t*)sm_l[0])[rp[it]] = lu;
    }

    for (int c = 0; c < NCHUNK; c++) {
        __syncthreads();
        const int cur = c & 1;
        const bool more = (c + 1 < NCHUNK);
        if (more) {
            const int koff = (c + 1) * KC;
#pragma unroll
            for (int it = 0; it < 8; it++) pf[it] = *(const float2*)(srcs[it] + koff);
        }
        uint32_t ah[2][4], al[2][4];
#pragma unroll
        for (int mt = 0; mt < 2; mt++) {
            const int mrow = mh * 32 + mt * 16 + grp;
            uint2 q0 = *(const uint2*)&sm_h[cur][mrow][tig * 2];
            uint2 q1 = *(const uint2*)&sm_h[cur][mrow + 8][tig * 2];
            ah[mt][0] = q0.x; ah[mt][2] = q0.y; ah[mt][1] = q1.x; ah[mt][3] = q1.y;
            uint2 s0 = *(const uint2*)&sm_l[cur][mrow][tig * 2];
            uint2 s1 = *(const uint2*)&sm_l[cur][mrow + 8][tig * 2];
            al[mt][0] = s0.x; al[mt][2] = s0.y; al[mt][1] = s1.x; al[mt][3] = s1.y;
        }
#pragma unroll
        for (int i = 0; i < 6; i++) {
            const int wrow = 64 + (nq * 6 + i) * 8 + grp;
            uint2 bh2 = *(const uint2*)&sm_h[cur][wrow][tig * 2];
            uint2 bl2 = *(const uint2*)&sm_l[cur][wrow][tig * 2];
            uint32_t bh[2] = {bh2.x, bh2.y};
            uint32_t bl[2] = {bl2.x, bl2.y};
#pragma unroll
            for (int mt = 0; mt < 2; mt++) {
                mma_bf16(acc[mt][i], al[mt], bh);
                mma_bf16(acc[mt][i], ah[mt], bl);
                mma_bf16(acc[mt][i], ah[mt], bh);
            }
        }
        if (more) {
            const int nxt = cur ^ 1;
#pragma unroll
            for (int it = 0; it < 8; it++) {
                uint32_t hu, lu;
                split2(pf[it].x, pf[it].y, hu, lu);
                ((uint32_t*)sm_h[nxt])[rp[it]] = hu;
                ((uint32_t*)sm_l[nxt])[rp[it]] = lu;
            }
        }
    }

#pragma unroll
    for (int mt = 0; mt < 2; mt++) {
        const int mwr = m0 + mh * 32 + mt * 16 + grp;
#pragma unroll
        for (int i = 0; i < 6; i++) {
            const int ntg = nq * 6 + i;
            const float a0 = acc[mt][i][0], a1 = acc[mt][i][1];
            const float a2 = acc[mt][i][2], a3 = acc[mt][i][3];
            if (ntg < 8) {
                const int col = ntg * 8 + tig * 2;
                *(float2*)&g_Q[(size_t)mwr * H_SZ + col]       = make_float2(a0, a1);
                *(float2*)&g_Q[(size_t)(mwr + 8) * H_SZ + col] = make_float2(a2, a3);
            } else {
                uint32_t* dh = (ntg < 16) ? g_Kh : g_Vh;
                uint32_t* dl = (ntg < 16) ? g_Kl : g_Vl;
                const int word = (ntg & 7) * 4 + tig;
                uint32_t hu, lu;
                split2(a0, a1, hu, lu);
                dh[(size_t)mwr * 32 + word] = hu;
                dl[(size_t)mwr * 32 + word] = lu;
                split2(a2, a3, hu, lu);
                dh[(size_t)(mwr + 8) * 32 + word] = hu;
                dl[(size_t)(mwr + 8) * 32 + word] = lu;
            }
        }
    }
}

// ---------------------------------------------------------------------------
// Flash-style sparse BigBird attention on tensor cores, cp.async
// DOUBLE-BUFFERED K/V tiles (gather of tile t+1 overlaps QK+PV of tile t).
// Math identical to the verified round-11 kernel.
// ---------------------------------------------------------------------------
#define QR 16
#define MAXC 1184
#define KST 36
#define SHIFT 12.0f
// dynamic smem layout (words): KH[2][64][KST] | KL | VH | VL | POOL[2*16*KST]
// then bytes: COLS[MAXC] u16 | RBIT[16][64] u32
#define TILE_W (64 * KST)                     // 2304 words per buffer
#define ARR_W  (2 * TILE_W)                   // 4608 words per array
#define POOL_W (2 * 16 * KST)                 // 1152 words
#define SMEM_ATTN ((4 * ARR_W + POOL_W) * 4 + MAXC * 2 + QR * 64 * 4)

__global__ __launch_bounds__(256) void attn16_kernel(
    const int* __restrict__ random_cols, float* __restrict__ out)
{
    extern __shared__ __align__(16) uint32_t dyn[];
    uint32_t* KH = dyn;
    uint32_t* KL = KH + ARR_W;
    uint32_t* VH = KL + ARR_W;
    uint32_t* VL = VH + ARR_W;
    uint32_t* POOL = VL + ARR_W;
    uint16_t* cols = (uint16_t*)(POOL + POOL_W);
    uint32_t* RBIT = (uint32_t*)(cols + MAXC);      // [16][64]

    __shared__ uint32_t ubit[64];
    __shared__ float lred[8][16];
    __shared__ int s_n;

    float* qs = (float*)POOL;
    uint32_t (*ph)[KST] = (uint32_t(*)[KST])POOL;
    uint32_t (*pl)[KST] = (uint32_t(*)[KST])(POOL + 16 * KST);

    const int blk = blockIdx.x;            // 0..1023
    const int b   = blk >> 7;
    const int r0  = (blk & 127) * QR;
    const int r3  = r0 + QR - 1;
    const int tid = threadIdx.x, wid = tid >> 5, lane = tid & 31;
    const int grp = lane >> 2, tig = lane & 3;
    const size_t bbase = (size_t)b * T_SZ;

    const int lo0 = max(0, r0 - (WIN - 1));
    const int gn  = min(NGLOB, r3 + 1);
    const int l0u = max(64, lo0);
    const int ln  = max(0, r3 - l0u + 1);

    // phase A: load scaled Q, zero bitmaps
    for (int i = tid; i < QR * 64; i += 256) {
        qs[i] = g_Q[(bbase + r0 + (i >> 6)) * H_SZ + (i & 63)] * 0.125f;
        RBIT[i] = 0;
    }
    if (tid < 64) ubit[tid] = 0;
    if (tid == 0) s_n = 0;
    __syncthreads();

    // phase B1: Q fragments (bf16 3-split)
    uint32_t aqh[4][4], aql[4][4];
#pragma unroll
    for (int ks = 0; ks < 4; ks++) {
        const float* qA = qs + grp * 64 + ks * 16 + 2 * tig;
        const float* qB = qs + (grp + 8) * 64 + ks * 16 + 2 * tig;
        split2(qA[0], qA[1], aqh[ks][0], aql[ks][0]);
        split2(qB[0], qB[1], aqh[ks][1], aql[ks][1]);
        split2(qA[8], qA[9], aqh[ks][2], aql[ks][2]);
        split2(qB[8], qB[9], aqh[ks][3], aql[ks][3]);
    }

    // phase B2: union column list + random bitmaps
    if (tid < gn) cols[tid] = (uint16_t)tid;
    if (tid >= 64 && tid < 64 + ln) cols[gn + tid - 64] = (uint16_t)(l0u + tid - 64);
    for (int i = tid; i < QR * NRAND; i += 256) {
        const int row = i >> 6;
        const int v = random_cols[(r0 + row) * NRAND + (i & 63)];
        atomicOr(&RBIT[row * 64 + (v >> 5)], 1u << (v & 31));
        if (v >= 64 && v < l0u) {
            const uint32_t bit = 1u << (v & 31);
            if (!(atomicOr(&ubit[v >> 5], bit) & bit))
                cols[gn + ln + atomicAdd(&s_n, 1)] = (uint16_t)v;
        }
    }
    __syncthreads();
    const int n = gn + ln + s_n;
    const int ntiles = (n + 63) >> 6;

    // gather helper: tile t into buffer buf (cp.async, 8x16B per thread)
    const int glc = tid >> 3;                 // 0..31 (base col)
    const int gch = (tid & 7) << 2;           // word offset 0..28
#define GATHER(T, BUF) do {                                                   \
        const int _t0 = (T) << 6;                                             \
        _Pragma("unroll")                                                     \
        for (int _e = 0; _e < 2; _e++) {                                      \
            const int _lc = glc + _e * 32;                                    \
            const int _idx = _t0 + _lc;                                       \
            const int _cg = (_idx < n) ? (int)cols[_idx] : 0;                 \
            const size_t _gb = (bbase + _cg) * 32 + gch;                      \
            const int _so = (BUF) * TILE_W + _lc * KST + gch;                 \
            cp16(&KH[_so], &g_Kh[_gb]);                                       \
            cp16(&KL[_so], &g_Kl[_gb]);                                       \
            cp16(&VH[_so], &g_Vh[_gb]);                                       \
            cp16(&VL[_so], &g_Vl[_gb]);                                       \
        }                                                                     \
        asm volatile("cp.async.commit_group;");                               \
    } while (0)

    GATHER(0, 0);
    asm volatile("cp.async.wait_group 0;");

    float oc[4] = {0.f, 0.f, 0.f, 0.f};
    float lA = 0.f, lB = 0.f;

    for (int t = 0; t < ntiles; t++) {
        __syncthreads();     // tile t visible everywhere; buf[(t+1)&1] free
        const int cur = t & 1;
        const int cbase = cur * TILE_W;

        if (t + 1 < ntiles) GATHER(t + 1, cur ^ 1);

        // QK
        float sc[4] = {0.f, 0.f, 0.f, 0.f};
        const int kr = (wid << 3) + grp;
#pragma unroll
        for (int ks = 0; ks < 4; ks++) {
            const int o = cbase + kr * KST + (ks << 3) + tig;
            uint32_t bh[2] = { KH[o], KH[o + 4] };
            uint32_t bl[2] = { KL[o], KL[o + 4] };
            mma_bf16(sc, aql[ks], bh);
            mma_bf16(sc, aqh[ks], bl);
            mma_bf16(sc, aqh[ks], bh);
        }

        // mask + exp (fixed shift) + row-sum partials
        const int iA = (t << 6) + (wid << 3) + (tig << 1);
        const int cA = (iA < n) ? (int)cols[iA] : -1;
        const int cB = (iA + 1 < n) ? (int)cols[iA + 1] : -1;
        const int rA = r0 + grp, rB = rA + 8;
#define OKM(r, c, rl) ((c) >= 0 && (c) <= (r) && ((c) > (r) - WIN || (c) < NGLOB || \
                       ((RBIT[(rl) * 64 + ((c) >> 5)] >> ((c) & 31)) & 1u)))
        const float p00 = OKM(rA, cA, grp)     ? __expf(sc[0] - SHIFT) : 0.f;
        const float p01 = OKM(rA, cB, grp)     ? __expf(sc[1] - SHIFT) : 0.f;
        const float p10 = OKM(rB, cA, grp + 8) ? __expf(sc[2] - SHIFT) : 0.f;
        const float p11 = OKM(rB, cB, grp + 8) ? __expf(sc[3] - SHIFT) : 0.f;
#undef OKM
        lA += p00 + p01;
        lB += p10 + p11;

        // store P (split, pair-permuted word position)
        {
            const int w = (wid << 2) + tig;
            const int pp = ((w >> 3) << 3) + ((w & 3) << 1) + ((w >> 2) & 1);
            uint32_t hw, lw;
            split2(p00, p01, hw, lw);
            ph[grp][pp] = hw; pl[grp][pp] = lw;
            split2(p10, p11, hw, lw);
            ph[grp + 8][pp] = hw; pl[grp + 8][pp] = lw;
        }
        __syncthreads();

        // PV
#pragma unroll
        for (int ks = 0; ks < 4; ks++) {
            uint32_t pah[4], pal[4];
            uint2 t0 = *(const uint2*)&ph[grp][(ks << 3) + (tig << 1)];
            uint2 t1 = *(const uint2*)&ph[grp + 8][(ks << 3) + (tig << 1)];
            pah[0] = t0.x; pah[2] = t0.y; pah[1] = t1.x; pah[3] = t1.y;
            uint2 t2 = *(const uint2*)&pl[grp][(ks << 3) + (tig << 1)];
            uint2 t3 = *(const uint2*)&pl[grp + 8][(ks << 3) + (tig << 1)];
            pal[0] = t2.x; pal[2] = t2.y; pal[1] = t3.x; pal[3] = t3.y;

            const int vo = cbase + ((ks << 4) + (lane & 15)) * KST + (wid << 2);
            uint32_t bvh[2], bvl[2];
            ldmx2t(bvh[0], bvh[1], (uint32_t)__cvta_generic_to_shared(&VH[vo]));
            ldmx2t(bvl[0], bvl[1], (uint32_t)__cvta_generic_to_shared(&VL[vo]));
            mma_bf16(oc, pal, bvh);
            mma_bf16(oc, pah, bvl);
            mma_bf16(oc, pah, bvh);
        }

        if (t + 1 < ntiles) asm volatile("cp.async.wait_group 0;");
    }

    // reduce row sums
    lA += __shfl_xor_sync(0xffffffffu, lA, 1);
    lA += __shfl_xor_sync(0xffffffffu, lA, 2);
    lB += __shfl_xor_sync(0xffffffffu, lB, 1);
    lB += __shfl_xor_sync(0xffffffffu, lB, 2);
    if (tig == 0) { lred[wid][grp] = lA; lred[wid][grp + 8] = lB; }
    __syncthreads();

    float sA = 0.f, sB = 0.f;
#pragma unroll
    for (int w2 = 0; w2 < 8; w2++) { sA += lred[w2][grp]; sB += lred[w2][grp + 8]; }

    const int dim = (wid << 3) + (tig << 1);
    const float iA2 = 1.f / sA, iB2 = 1.f / sB;
    *(float2*)&out[(bbase + r0 + grp) * H_SZ + dim] =
        make_float2(oc[0] * iA2, oc[1] * iA2);
    *(float2*)&out[(bbase + r0 + grp + 8) * H_SZ + dim] =
        make_float2(oc[2] * iB2, oc[3] * iB2);
}

// ---------------------------------------------------------------------------
// kernel_launch — inputs per metadata order: x, random_cols, Wk, Wq, Wv
// ---------------------------------------------------------------------------
extern "C" void kernel_launch(void* const* d_in, const int* in_sizes, int n_in,
                              void* d_out, int out_size)
{
    const float* x           = (const float*)d_in[0];
    const int*   random_cols = (const int*)  d_in[1];
    const float* Wk          = (const float*)d_in[2];
    const float* Wq          = (const float*)d_in[3];
    const float* Wv          = (const float*)d_in[4];
    float* out = (float*)d_out;

    static bool attr_set = false;
    if (!attr_set) {
        cudaFuncSetAttribute(attn16_kernel,
                             cudaFuncAttributeMaxDynamicSharedMemorySize,
                             SMEM_ATTN);
        attr_set = true;
    }

    proj_tc_kernel<<<BT / 64, 256>>>(x, Wq, Wk, Wv);
    attn16_kernel<<<BT / QR, 256, SMEM_ATTN>>>(random_cols, out);
}

// round 13
// speedup vs baseline: 1.1246x; 1.0941x over previous
#include <cuda_runtime.h>
#include <cuda_bf16.h>
#include <math.h>
#include <stdint.h>

#define B_SZ 8
#define T_SZ 2048
#define C_SZ 1024
#define H_SZ 64
#define WIN 64
#define NGLOB 64
#define NRAND 64
#define BT (B_SZ * T_SZ)

// Scratch: Q fp32; K,V pre-split bf16 hi/lo (bf16x2 words, 32 per token).
__device__ float    g_Q [BT * H_SZ];
__device__ uint32_t g_Kh[BT * 32];
__device__ uint32_t g_Kl[BT * 32];
__device__ uint32_t g_Vh[BT * 32];
__device__ uint32_t g_Vl[BT * 32];

__device__ __forceinline__ void mma_bf16(float* c, const uint32_t* a, const uint32_t* b) {
    asm volatile(
        "mma.sync.aligned.m16n8k16.row.col.f32.bf16.bf16.f32 "
        "{%0,%1,%2,%3}, {%4,%5,%6,%7}, {%8,%9}, {%0,%1,%2,%3};"
        : "+f"(c[0]), "+f"(c[1]), "+f"(c[2]), "+f"(c[3])
        : "r"(a[0]), "r"(a[1]), "r"(a[2]), "r"(a[3]), "r"(b[0]), "r"(b[1]));
}

__device__ __forceinline__ void ldmx2t(uint32_t& r0, uint32_t& r1, uint32_t addr) {
    asm volatile("ldmatrix.sync.aligned.m8n8.x2.trans.shared.b16 {%0,%1}, [%2];"
                 : "=r"(r0), "=r"(r1) : "r"(addr));
}

__device__ __forceinline__ void split2(float a, float b, uint32_t& hw, uint32_t& lw) {
    __nv_bfloat162 h2 = __floats2bfloat162_rn(a, b);
    hw = *(uint32_t*)&h2;
    float ra = a - __uint_as_float(hw << 16);
    float rb = b - __uint_as_float(hw & 0xFFFF0000u);
    __nv_bfloat162 l2 = __floats2bfloat162_rn(ra, rb);
    lw = *(uint32_t*)&l2;
}

__device__ __forceinline__ void cp16(void* smem_dst, const void* gsrc) {
    uint32_t sa = (uint32_t)__cvta_generic_to_shared(smem_dst);
    asm volatile("cp.async.cg.shared.global [%0], [%1], 16;" :: "r"(sa), "l"(gsrc));
}

__device__ __forceinline__ float bflo(uint32_t w) { return __uint_as_float(w << 16); }
__device__ __forceinline__ float bfhi(uint32_t w) { return __uint_as_float(w & 0xFFFF0000u); }

// ---------------------------------------------------------------------------
// FUSED projection GEMM (Q,K,V), bf16 3-split, ping-pong smem (verified).
// ---------------------------------------------------------------------------
#define KC 16
#define PADK 12
#define NCHUNK (C_SZ / KC)

__global__ __launch_bounds__(256, 2) void proj_tc_kernel(
    const float* __restrict__ x, const float* __restrict__ Wq,
    const float* __restrict__ Wk, const float* __restrict__ Wv)
{
    __shared__ __align__(16) uint32_t sm_h[2][256][PADK];
    __shared__ __align__(16) uint32_t sm_l[2][256][PADK];

    const int m0 = blockIdx.x * 64;
    const int tid = threadIdx.x, warp = tid >> 5, lane = tid & 31;
    const int grp = lane >> 2, tig = lane & 3;
    const int mh = warp & 1, nq = warp >> 1;

    const float* srcs[8];
    int rp[8];
#pragma unroll
    for (int it = 0; it < 8; it++) {
        const int i = it * 256 + tid;
        int r, w; const float* base;
        if (it < 2) {
            r = i >> 3; w = i & 7;
            base = &x[(size_t)(m0 + r) * C_SZ];
            rp[it] = r * PADK;
        } else {
            const int j = i - 512;
            r = j >> 3; w = j & 7;
            base = (r < 64) ? &Wq[(size_t)r * C_SZ]
                 : (r < 128) ? &Wk[(size_t)(r - 64) * C_SZ]
                             : &Wv[(size_t)(r - 128) * C_SZ];
            rp[it] = (64 + r) * PADK;
        }
        srcs[it] = base + w * 2;
        rp[it] += 2 * (w & 3) + (w >> 2);
    }

    float acc[2][6][4];
#pragma unroll
    for (int mt = 0; mt < 2; mt++)
#pragma unroll
        for (int i = 0; i < 6; i++)
#pragma unroll
            for (int j = 0; j < 4; j++) acc[mt][i][j] = 0.f;

    float2 pf[8];
#pragma unroll
    for (int it = 0; it < 8; it++) pf[it] = *(const float2*)srcs[it];
#pragma unroll
    for (int it = 0; it < 8; it++) {
        uint32_t hu, lu;
        split2(pf[it].x, pf[it].y, hu, lu);
        ((uint32_t*)sm_h[0])[rp[it]] = hu;
        ((uint32_t*)sm_l[0])[rp[it]] = lu;
    }

    for (int c = 0; c < NCHUNK; c++) {
        __syncthreads();
        const int cur = c & 1;
        const bool more = (c + 1 < NCHUNK);
        if (more) {
            const int koff = (c + 1) * KC;
#pragma unroll
            for (int it = 0; it < 8; it++) pf[it] = *(const float2*)(srcs[it] + koff);
        }
        uint32_t ah[2][4], al[2][4];
#pragma unroll
        for (int mt = 0; mt < 2; mt++) {
            const int mrow = mh * 32 + mt * 16 + grp;
            uint2 q0 = *(const uint2*)&sm_h[cur][mrow][tig * 2];
            uint2 q1 = *(const uint2*)&sm_h[cur][mrow + 8][tig * 2];
            ah[mt][0] = q0.x; ah[mt][2] = q0.y; ah[mt][1] = q1.x; ah[mt][3] = q1.y;
            uint2 s0 = *(const uint2*)&sm_l[cur][mrow][tig * 2];
            uint2 s1 = *(const uint2*)&sm_l[cur][mrow + 8][tig * 2];
            al[mt][0] = s0.x; al[mt][2] = s0.y; al[mt][1] = s1.x; al[mt][3] = s1.y;
        }
#pragma unroll
        for (int i = 0; i < 6; i++) {
            const int wrow = 64 + (nq * 6 + i) * 8 + grp;
            uint2 bh2 = *(const uint2*)&sm_h[cur][wrow][tig * 2];
            uint2 bl2 = *(const uint2*)&sm_l[cur][wrow][tig * 2];
            uint32_t bh[2] = {bh2.x, bh2.y};
            uint32_t bl[2] = {bl2.x, bl2.y};
#pragma unroll
            for (int mt = 0; mt < 2; mt++) {
                mma_bf16(acc[mt][i], al[mt], bh);
                mma_bf16(acc[mt][i], ah[mt], bl);
                mma_bf16(acc[mt][i], ah[mt], bh);
            }
        }
        if (more) {
            const int nxt = cur ^ 1;
#pragma unroll
            for (int it = 0; it < 8; it++) {
                uint32_t hu, lu;
                split2(pf[it].x, pf[it].y, hu, lu);
                ((uint32_t*)sm_h[nxt])[rp[it]] = hu;
                ((uint32_t*)sm_l[nxt])[rp[it]] = lu;
            }
        }
    }

#pragma unroll
    for (int mt = 0; mt < 2; mt++) {
        const int mwr = m0 + mh * 32 + mt * 16 + grp;
#pragma unroll
        for (int i = 0; i < 6; i++) {
            const int ntg = nq * 6 + i;
            const float a0 = acc[mt][i][0], a1 = acc[mt][i][1];
            const float a2 = acc[mt][i][2], a3 = acc[mt][i][3];
            if (ntg < 8) {
                const int col = ntg * 8 + tig * 2;
                *(float2*)&g_Q[(size_t)mwr * H_SZ + col]       = make_float2(a0, a1);
                *(float2*)&g_Q[(size_t)(mwr + 8) * H_SZ + col] = make_float2(a2, a3);
            } else {
                uint32_t* dh = (ntg < 16) ? g_Kh : g_Vh;
                uint32_t* dl = (ntg < 16) ? g_Kl : g_Vl;
                const int word = (ntg & 7) * 4 + tig;
                uint32_t hu, lu;
                split2(a0, a1, hu, lu);
                dh[(size_t)mwr * 32 + word] = hu;
                dl[(size_t)mwr * 32 + word] = lu;
                split2(a2, a3, hu, lu);
                dh[(size_t)(mwr + 8) * 32 + word] = hu;
                dl[(size_t)(mwr + 8) * 32 + word] = lu;
            }
        }
    }
}

// ---------------------------------------------------------------------------
// Hybrid sparse BigBird attention:
//  - dense part (global [0,gn) + local [l0u,r3], <=3 tiles) via verified MMA
//    path with fixed-shift softmax exp(s-12);
//  - random extras (c in [64,l0u), disjoint from dense, auto-causal) via
//    per-row deduped lists + scalar 8-lane dot groups (fp32 from hi+lo).
//  Contributions are additive (same fixed shift); merged in the epilogue.
// ---------------------------------------------------------------------------
#define QR 16
#define NDENSE 192
#define KST 36
#define SHIFT 12.0f
#define TILE_W (64 * KST)          // 2304 words
#define POOL_W (2 * 16 * KST)      // 1152 words (PH|PL)
// words: KH|KL|VH|VL (TILE_W each) | POOL | QS 1024 | OR 1024 | RBIT 1024
// then u16: cols[192] | rlist[16*64]
#define SMEM_ATTN ((4 * TILE_W + POOL_W + 3 * 1024) * 4 + (NDENSE + QR * 64) * 2)

__global__ __launch_bounds__(256) void attn16_kernel(
    const int* __restrict__ random_cols, float* __restrict__ out)
{
    extern __shared__ __align__(16) uint32_t dyn[];
    uint32_t* KH = dyn;
    uint32_t* KL = KH + TILE_W;
    uint32_t* VH = KL + TILE_W;
    uint32_t* VL = VH + TILE_W;
    uint32_t* POOL = VL + TILE_W;
    float*    QS  = (float*)(POOL + POOL_W);        // [16][64] scaled q
    float*    OR_ = QS + 1024;                      // [16][64] random-part O
    uint32_t* RBIT = (uint32_t*)(OR_ + 1024);       // [16][64]
    uint16_t* cols  = (uint16_t*)(RBIT + 1024);     // dense cols
    uint16_t* rlist = cols + NDENSE;                // [16][64] per-row extras

    __shared__ float lred[8][16];
    __shared__ float l_r[16];
    __shared__ int rcnt[16];

    uint32_t (*ph)[KST] = (uint32_t(*)[KST])POOL;
    uint32_t (*pl)[KST] = (uint32_t(*)[KST])(POOL + 16 * KST);

    const int blk = blockIdx.x;            // 0..1023
    const int b   = blk >> 7;
    const int r0  = (blk & 127) * QR;
    const int r3  = r0 + QR - 1;
    const int tid = threadIdx.x, wid = tid >> 5, lane = tid & 31;
    const int grp = lane >> 2, tig = lane & 3;
    const int l8 = lane & 7, g8 = lane >> 3;
    const size_t bbase = (size_t)b * T_SZ;

    const int lo0 = max(0, r0 - (WIN - 1));
    const int gn  = min(NGLOB, r3 + 1);
    const int l0u = max(64, lo0);
    const int ln  = max(0, r3 - l0u + 1);
    const int nd  = gn + ln;                 // dense count (<=143)
    const int ndt = (nd + 63) >> 6;          // <=3

    // phase A: load scaled Q, zero OR/RBIT, counters
    for (int i = tid; i < QR * 64; i += 256) {
        QS[i] = g_Q[(bbase + r0 + (i >> 6)) * H_SZ + (i & 63)] * 0.125f;
        OR_[i] = 0.f;
        RBIT[i] = 0;
    }
    if (tid < 16) { rcnt[tid] = 0; l_r[tid] = 0.f; }
    __syncthreads();

    // Q fragments (bf16 3-split)
    uint32_t aqh[4][4], aql[4][4];
#pragma unroll
    for (int ks = 0; ks < 4; ks++) {
        const float* qA = QS + grp * 64 + ks * 16 + 2 * tig;
        const float* qB = QS + (grp + 8) * 64 + ks * 16 + 2 * tig;
        split2(qA[0], qA[1], aqh[ks][0], aql[ks][0]);
        split2(qB[0], qB[1], aqh[ks][1], aql[ks][1]);
        split2(qA[8], qA[9], aqh[ks][2], aql[ks][2]);
        split2(qB[8], qB[9], aqh[ks][3], aql[ks][3]);
    }

    // dense cols + random bitmaps/per-row extra lists
    if (tid < gn) cols[tid] = (uint16_t)tid;
    if (tid >= 64 && tid < 64 + ln) cols[gn + tid - 64] = (uint16_t)(l0u + tid - 64);
    for (int i = tid; i < QR * NRAND; i += 256) {
        const int row = i >> 6;
        const int v = random_cols[(r0 + row) * NRAND + (i & 63)];
        const uint32_t bit = 1u << (v & 31);
        const uint32_t old = atomicOr(&RBIT[row * 64 + (v >> 5)], bit);
        if (v >= 64 && v < l0u && !(old & bit))
            rlist[row * 64 + atomicAdd(&rcnt[row], 1)] = (uint16_t)v;
    }
    __syncthreads();

    // dense gather (single buffer, cp.async)
    const int glc = tid >> 3;
    const int gch = (tid & 7) << 2;
#define GATHER(T) do {                                                        \
        const int _t0 = (T) << 6;                                             \
        _Pragma("unroll")                                                     \
        for (int _e = 0; _e < 2; _e++) {                                      \
            const int _lc = glc + _e * 32;                                    \
            const int _idx = _t0 + _lc;                                       \
            const int _cg = (_idx < nd) ? (int)cols[_idx] : 0;                \
            const size_t _gb = (bbase + _cg) * 32 + gch;                      \
            const int _so = _lc * KST + gch;                                  \
            cp16(&KH[_so], &g_Kh[_gb]);                                       \
            cp16(&KL[_so], &g_Kl[_gb]);                                       \
            cp16(&VH[_so], &g_Vh[_gb]);                                       \
            cp16(&VL[_so], &g_Vl[_gb]);                                       \
        }                                                                     \
        asm volatile("cp.async.commit_group;");                               \
        asm volatile("cp.async.wait_group 0;");                               \
    } while (0)

    GATHER(0);

    float oc[4] = {0.f, 0.f, 0.f, 0.f};
    float lA = 0.f, lB = 0.f;

    for (int t = 0; t < ndt; t++) {
        __syncthreads();    // tile visible

        // QK
        float sc[4] = {0.f, 0.f, 0.f, 0.f};
        const int kr = (wid << 3) + grp;
#pragma unroll
        for (int ks = 0; ks < 4; ks++) {
            const int o = kr * KST + (ks << 3) + tig;
            uint32_t bh[2] = { KH[o], KH[o + 4] };
            uint32_t bl[2] = { KL[o], KL[o + 4] };
            mma_bf16(sc, aql[ks], bh);
            mma_bf16(sc, aqh[ks], bl);
            mma_bf16(sc, aqh[ks], bh);
        }

        const int iA = (t << 6) + (wid << 3) + (tig << 1);
        const int cA = (iA < nd) ? (int)cols[iA] : -1;
        const int cB = (iA + 1 < nd) ? (int)cols[iA + 1] : -1;
        const int rA = r0 + grp, rB = rA + 8;
#define OKM(r, c, rl) ((c) >= 0 && (c) <= (r) && ((c) > (r) - WIN || (c) < NGLOB || \
                       ((RBIT[(rl) * 64 + ((c) >> 5)] >> ((c) & 31)) & 1u)))
        const float p00 = OKM(rA, cA, grp)     ? __expf(sc[0] - SHIFT) : 0.f;
        const float p01 = OKM(rA, cB, grp)     ? __expf(sc[1] - SHIFT) : 0.f;
        const float p10 = OKM(rB, cA, grp + 8) ? __expf(sc[2] - SHIFT) : 0.f;
        const float p11 = OKM(rB, cB, grp + 8) ? __expf(sc[3] - SHIFT) : 0.f;
#undef OKM
        lA += p00 + p01;
        lB += p10 + p11;

        // store P (split, pair-permuted)
        {
            const int w = (wid << 2) + tig;
            const int pp = ((w >> 3) << 3) + ((w & 3) << 1) + ((w >> 2) & 1);
            uint32_t hw, lw;
            split2(p00, p01, hw, lw);
            ph[grp][pp] = hw; pl[grp][pp] = lw;
            split2(p10, p11, hw, lw);
            ph[grp + 8][pp] = hw; pl[grp + 8][pp] = lw;
        }
        __syncthreads();

        // PV
#pragma unroll
        for (int ks = 0; ks < 4; ks++) {
            uint32_t pah[4], pal[4];
            uint2 t0 = *(const uint2*)&ph[grp][(ks << 3) + (tig << 1)];
            uint2 t1 = *(const uint2*)&ph[grp + 8][(ks << 3) + (tig << 1)];
            pah[0] = t0.x; pah[2] = t0.y; pah[1] = t1.x; pah[3] = t1.y;
            uint2 t2 = *(const uint2*)&pl[grp][(ks << 3) + (tig << 1)];
            uint2 t3 = *(const uint2*)&pl[grp + 8][(ks << 3) + (tig << 1)];
            pal[0] = t2.x; pal[2] = t2.y; pal[1] = t3.x; pal[3] = t3.y;

            const int vo = ((ks << 4) + (lane & 15)) * KST + (wid << 2);
            uint32_t bvh[2], bvl[2];
            ldmx2t(bvh[0], bvh[1], (uint32_t)__cvta_generic_to_shared(&VH[vo]));
            ldmx2t(bvl[0], bvl[1], (uint32_t)__cvta_generic_to_shared(&VL[vo]));
            mma_bf16(oc, pal, bvh);
            mma_bf16(oc, pah, bvl);
            mma_bf16(oc, pah, bvh);
        }
        __syncthreads();    // buffer free

        if (t + 1 < ndt) GATHER(t + 1);
    }

    // ---- scalar phase: per-row random extras (zero redundancy) ----
#pragma unroll
    for (int half = 0; half < 2; half++) {
        const int rr = wid + half * 8;
        const int cnt = rcnt[rr];
        float qreg[8];
#pragma unroll
        for (int d = 0; d < 8; d++) qreg[d] = QS[rr * 64 + 8 * l8 + d];
        float o8[8] = {0.f,0.f,0.f,0.f,0.f,0.f,0.f,0.f};
        float lp = 0.f;

        for (int j0 = 0; j0 < cnt; j0 += 4) {       // warp-uniform bound
            const int j = j0 + g8;
            const bool act = (j < cnt);
            const int c = (int)rlist[rr * 64 + (act ? j : 0)];
            const size_t gb = (bbase + c) * 32 + 4 * l8;
            const uint4 khw = *(const uint4*)&g_Kh[gb];
            const uint4 klw = *(const uint4*)&g_Kl[gb];
            const uint4 vhw = *(const uint4*)&g_Vh[gb];
            const uint4 vlw = *(const uint4*)&g_Vl[gb];

            float p = qreg[0] * (bflo(khw.x) + bflo(klw.x))
                    + qreg[1] * (bfhi(khw.x) + bfhi(klw.x))
                    + qreg[2] * (bflo(khw.y) + bflo(klw.y))
                    + qreg[3] * (bfhi(khw.y) + bfhi(klw.y))
                    + qreg[4] * (bflo(khw.z) + bflo(klw.z))
                    + qreg[5] * (bfhi(khw.z) + bfhi(klw.z))
                    + qreg[6] * (bflo(khw.w) + bflo(klw.w))
                    + qreg[7] * (bfhi(khw.w) + bfhi(klw.w));
            p += __shfl_xor_sync(0xffffffffu, p, 1);
            p += __shfl_xor_sync(0xffffffffu, p, 2);
            p += __shfl_xor_sync(0xffffffffu, p, 4);
            const float wgt = act ? __expf(p - SHIFT) : 0.f;
            if (l8 == 0) lp += wgt;
            o8[0] += wgt * (bflo(vhw.x) + bflo(vlw.x));
            o8[1] += wgt * (bfhi(vhw.x) + bfhi(vlw.x));
            o8[2] += wgt * (bflo(vhw.y) + bflo(vlw.y));
            o8[3] += wgt * (bfhi(vhw.y) + bfhi(vlw.y));
            o8[4] += wgt * (bflo(vhw.z) + bflo(vlw.z));
            o8[5] += wgt * (bfhi(vhw.z) + bfhi(vlw.z));
            o8[6] += wgt * (bflo(vhw.w) + bflo(vlw.w));
            o8[7] += wgt * (bfhi(vhw.w) + bfhi(vlw.w));
        }
        // reduce 4 groups (lanes with same l8)
#pragma unroll
        for (int d = 0; d < 8; d++) {
            o8[d] += __shfl_xor_sync(0xffffffffu, o8[d], 8);
            o8[d] += __shfl_xor_sync(0xffffffffu, o8[d], 16);
        }
        lp += __shfl_xor_sync(0xffffffffu, lp, 8);
        lp += __shfl_xor_sync(0xffffffffu, lp, 16);
        if (g8 == 0) {
#pragma unroll
            for (int d = 0; d < 8; d++) OR_[rr * 64 + 8 * l8 + d] = o8[d];
            if (l8 == 0) l_r[rr] = lp;
        }
    }

    // dense row-sum reduction
    lA += __shfl_xor_sync(0xffffffffu, lA, 1);
    lA += __shfl_xor_sync(0xffffffffu, lA, 2);
    lB += __shfl_xor_sync(0xffffffffu, lB, 1);
    lB += __shfl_xor_sync(0xffffffffu, lB, 2);
    if (tig == 0) { lred[wid][grp] = lA; lred[wid][grp + 8] = lB; }
    __syncthreads();

    float sA = l_r[grp], sB = l_r[grp + 8];
#pragma unroll
    for (int w2 = 0; w2 < 8; w2++) { sA += lred[w2][grp]; sB += lred[w2][grp + 8]; }

    const int dim = (wid << 3) + (tig << 1);
    const float iA2 = 1.f / sA, iB2 = 1.f / sB;
    *(float2*)&out[(bbase + r0 + grp) * H_SZ + dim] =
        make_float2((oc[0] + OR_[grp * 64 + dim]) * iA2,
                    (oc[1] + OR_[grp * 64 + dim + 1]) * iA2);
    *(float2*)&out[(bbase + r0 + grp + 8) * H_SZ + dim] =
        make_float2((oc[2] + OR_[(grp + 8) * 64 + dim]) * iB2,
                    (oc[3] + OR_[(grp + 8) * 64 + dim + 1]) * iB2);
}

// ---------------------------------------------------------------------------
// kernel_launch — inputs per metadata order: x, random_cols, Wk, Wq, Wv
// ---------------------------------------------------------------------------
extern "C" void kernel_launch(void* const* d_in, const int* in_sizes, int n_in,
                              void* d_out, int out_size)
{
    const float* x           = (const float*)d_in[0];
    const int*   random_cols = (const int*)  d_in[1];
    const float* Wk          = (const float*)d_in[2];
    const float* Wq          = (const float*)d_in[3];
    const float* Wv          = (const float*)d_in[4];
    float* out = (float*)d_out;

    static bool attr_set = false;
    if (!attr_set) {
        cudaFuncSetAttribute(attn16_kernel,
                             cudaFuncAttributeMaxDynamicSharedMemorySize,
                             SMEM_ATTN);
        attr_set = true;
    }

    proj_tc_kernel<<<BT / 64, 256>>>(x, Wq, Wk, Wv);
    attn16_kernel<<<BT / QR, 256, SMEM_ATTN>>>(random_cols, out);
}

// round 14
// speedup vs baseline: 1.1643x; 1.0353x over previous
#include <cuda_runtime.h>
#include <cuda_bf16.h>
#include <math.h>
#include <stdint.h>

#define B_SZ 8
#define T_SZ 2048
#define C_SZ 1024
#define H_SZ 64
#define WIN 64
#define NGLOB 64
#define NRAND 64
#define BT (B_SZ * T_SZ)

// Scratch: Q fp32; K,V pre-split bf16 hi/lo (bf16x2 words, 32 per token).
__device__ float    g_Q [BT * H_SZ];
__device__ uint32_t g_Kh[BT * 32];
__device__ uint32_t g_Kl[BT * 32];
__device__ uint32_t g_Vh[BT * 32];
__device__ uint32_t g_Vl[BT * 32];

__device__ __forceinline__ void mma_bf16(float* c, const uint32_t* a, const uint32_t* b) {
    asm volatile(
        "mma.sync.aligned.m16n8k16.row.col.f32.bf16.bf16.f32 "
        "{%0,%1,%2,%3}, {%4,%5,%6,%7}, {%8,%9}, {%0,%1,%2,%3};"
        : "+f"(c[0]), "+f"(c[1]), "+f"(c[2]), "+f"(c[3])
        : "r"(a[0]), "r"(a[1]), "r"(a[2]), "r"(a[3]), "r"(b[0]), "r"(b[1]));
}

__device__ __forceinline__ void ldmx2t(uint32_t& r0, uint32_t& r1, uint32_t addr) {
    asm volatile("ldmatrix.sync.aligned.m8n8.x2.trans.shared.b16 {%0,%1}, [%2];"
                 : "=r"(r0), "=r"(r1) : "r"(addr));
}

__device__ __forceinline__ void split2(float a, float b, uint32_t& hw, uint32_t& lw) {
    __nv_bfloat162 h2 = __floats2bfloat162_rn(a, b);
    hw = *(uint32_t*)&h2;
    float ra = a - __uint_as_float(hw << 16);
    float rb = b - __uint_as_float(hw & 0xFFFF0000u);
    __nv_bfloat162 l2 = __floats2bfloat162_rn(ra, rb);
    lw = *(uint32_t*)&l2;
}

__device__ __forceinline__ void cp16(void* smem_dst, const void* gsrc) {
    uint32_t sa = (uint32_t)__cvta_generic_to_shared(smem_dst);
    asm volatile("cp.async.cg.shared.global [%0], [%1], 16;" :: "r"(sa), "l"(gsrc));
}

__device__ __forceinline__ float bflo(uint32_t w) { return __uint_as_float(w << 16); }
__device__ __forceinline__ float bfhi(uint32_t w) { return __uint_as_float(w & 0xFFFF0000u); }

// ---------------------------------------------------------------------------
// FUSED projection GEMM (Q,K,V), bf16 3-split, ping-pong smem.
// MMA phase reordered SPLIT-MAJOR with preloaded b-frags: same-accumulator
// RAW distance = 12 MMAs (was 2-3) -> no tensor-pipe dependency stalls.
// ---------------------------------------------------------------------------
#define KC 16
#define PADK 12
#define NCHUNK (C_SZ / KC)

__global__ __launch_bounds__(256, 2) void proj_tc_kernel(
    const float* __restrict__ x, const float* __restrict__ Wq,
    const float* __restrict__ Wk, const float* __restrict__ Wv)
{
    __shared__ __align__(16) uint32_t sm_h[2][256][PADK];
    __shared__ __align__(16) uint32_t sm_l[2][256][PADK];

    const int m0 = blockIdx.x * 64;
    const int tid = threadIdx.x, warp = tid >> 5, lane = tid & 31;
    const int grp = lane >> 2, tig = lane & 3;
    const int mh = warp & 1, nq = warp >> 1;

    const float* srcs[8];
    int rp[8];
#pragma unroll
    for (int it = 0; it < 8; it++) {
        const int i = it * 256 + tid;
        int r, w; const float* base;
        if (it < 2) {
            r = i >> 3; w = i & 7;
            base = &x[(size_t)(m0 + r) * C_SZ];
            rp[it] = r * PADK;
        } else {
            const int j = i - 512;
            r = j >> 3; w = j & 7;
            base = (r < 64) ? &Wq[(size_t)r * C_SZ]
                 : (r < 128) ? &Wk[(size_t)(r - 64) * C_SZ]
                             : &Wv[(size_t)(r - 128) * C_SZ];
            rp[it] = (64 + r) * PADK;
        }
        srcs[it] = base + w * 2;
        rp[it] += 2 * (w & 3) + (w >> 2);
    }

    float acc[2][6][4];
#pragma unroll
    for (int mt = 0; mt < 2; mt++)
#pragma unroll
        for (int i = 0; i < 6; i++)
#pragma unroll
            for (int j = 0; j < 4; j++) acc[mt][i][j] = 0.f;

    float2 pf[8];
#pragma unroll
    for (int it = 0; it < 8; it++) pf[it] = *(const float2*)srcs[it];
#pragma unroll
    for (int it = 0; it < 8; it++) {
        uint32_t hu, lu;
        split2(pf[it].x, pf[it].y, hu, lu);
        ((uint32_t*)sm_h[0])[rp[it]] = hu;
        ((uint32_t*)sm_l[0])[rp[it]] = lu;
    }

    for (int c = 0; c < NCHUNK; c++) {
        __syncthreads();
        const int cur = c & 1;
        const bool more = (c + 1 < NCHUNK);
        if (more) {
            const int koff = (c + 1) * KC;
#pragma unroll
            for (int it = 0; it < 8; it++) pf[it] = *(const float2*)(srcs[it] + koff);
        }
        uint32_t ah[2][4], al[2][4];
#pragma unroll
        for (int mt = 0; mt < 2; mt++) {
            const int mrow = mh * 32 + mt * 16 + grp;
            uint2 q0 = *(const uint2*)&sm_h[cur][mrow][tig * 2];
            uint2 q1 = *(const uint2*)&sm_h[cur][mrow + 8][tig * 2];
            ah[mt][0] = q0.x; ah[mt][2] = q0.y; ah[mt][1] = q1.x; ah[mt][3] = q1.y;
            uint2 s0 = *(const uint2*)&sm_l[cur][mrow][tig * 2];
            uint2 s1 = *(const uint2*)&sm_l[cur][mrow + 8][tig * 2];
            al[mt][0] = s0.x; al[mt][2] = s0.y; al[mt][1] = s1.x; al[mt][3] = s1.y;
        }
        // preload all b-fragments, then split-major MMA issue
        uint32_t bh[6][2], bl[6][2];
#pragma unroll
        for (int i = 0; i < 6; i++) {
            const int wrow = 64 + (nq * 6 + i) * 8 + grp;
            uint2 bh2 = *(const uint2*)&sm_h[cur][wrow][tig * 2];
            uint2 bl2 = *(const uint2*)&sm_l[cur][wrow][tig * 2];
            bh[i][0] = bh2.x; bh[i][1] = bh2.y;
            bl[i][0] = bl2.x; bl[i][1] = bl2.y;
        }
#pragma unroll
        for (int i = 0; i < 6; i++)
#pragma unroll
            for (int mt = 0; mt < 2; mt++)
                mma_bf16(acc[mt][i], al[mt], bh[i]);
#pragma unroll
        for (int i = 0; i < 6; i++)
#pragma unroll
            for (int mt = 0; mt < 2; mt++)
                mma_bf16(acc[mt][i], ah[mt], bl[i]);
#pragma unroll
        for (int i = 0; i < 6; i++)
#pragma unroll
            for (int mt = 0; mt < 2; mt++)
                mma_bf16(acc[mt][i], ah[mt], bh[i]);

        if (more) {
            const int nxt = cur ^ 1;
#pragma unroll
            for (int it = 0; it < 8; it++) {
                uint32_t hu, lu;
                split2(pf[it].x, pf[it].y, hu, lu);
                ((uint32_t*)sm_h[nxt])[rp[it]] = hu;
                ((uint32_t*)sm_l[nxt])[rp[it]] = lu;
            }
        }
    }

#pragma unroll
    for (int mt = 0; mt < 2; mt++) {
        const int mwr = m0 + mh * 32 + mt * 16 + grp;
#pragma unroll
        for (int i = 0; i < 6; i++) {
            const int ntg = nq * 6 + i;
            const float a0 = acc[mt][i][0], a1 = acc[mt][i][1];
            const float a2 = acc[mt][i][2], a3 = acc[mt][i][3];
            if (ntg < 8) {
                const int col = ntg * 8 + tig * 2;
                *(float2*)&g_Q[(size_t)mwr * H_SZ + col]       = make_float2(a0, a1);
                *(float2*)&g_Q[(size_t)(mwr + 8) * H_SZ + col] = make_float2(a2, a3);
            } else {
                uint32_t* dh = (ntg < 16) ? g_Kh : g_Vh;
                uint32_t* dl = (ntg < 16) ? g_Kl : g_Vl;
                const int word = (ntg & 7) * 4 + tig;
                uint32_t hu, lu;
                split2(a0, a1, hu, lu);
                dh[(size_t)mwr * 32 + word] = hu;
                dl[(size_t)mwr * 32 + word] = lu;
                split2(a2, a3, hu, lu);
                dh[(size_t)(mwr + 8) * 32 + word] = hu;
                dl[(size_t)(mwr + 8) * 32 + word] = lu;
            }
        }
    }
}

// ---------------------------------------------------------------------------
// Hybrid sparse BigBird attention (dense MMA part + per-row scalar randoms).
// QK/PV now use 3 accumulator sets (one per split term) so MMA RAW chains
// are depth-4/distance-3 instead of depth-12/distance-1.
// ---------------------------------------------------------------------------
#define QR 16
#define NDENSE 192
#define KST 36
#define SHIFT 12.0f
#define TILE_W (64 * KST)
#define POOL_W (2 * 16 * KST)
#define SMEM_ATTN ((4 * TILE_W + POOL_W + 3 * 1024) * 4 + (NDENSE + QR * 64) * 2)

__global__ __launch_bounds__(256, 3) void attn16_kernel(
    const int* __restrict__ random_cols, float* __restrict__ out)
{
    extern __shared__ __align__(16) uint32_t dyn[];
    uint32_t* KH = dyn;
    uint32_t* KL = KH + TILE_W;
    uint32_t* VH = KL + TILE_W;
    uint32_t* VL = VH + TILE_W;
    uint32_t* POOL = VL + TILE_W;
    float*    QS  = (float*)(POOL + POOL_W);
    float*    OR_ = QS + 1024;
    uint32_t* RBIT = (uint32_t*)(OR_ + 1024);
    uint16_t* cols  = (uint16_t*)(RBIT + 1024);
    uint16_t* rlist = cols + NDENSE;

    __shared__ float lred[8][16];
    __shared__ float l_r[16];
    __shared__ int rcnt[16];

    uint32_t (*ph)[KST] = (uint32_t(*)[KST])POOL;
    uint32_t (*pl)[KST] = (uint32_t(*)[KST])(POOL + 16 * KST);

    const int blk = blockIdx.x;
    const int b   = blk >> 7;
    const int r0  = (blk & 127) * QR;
    const int r3  = r0 + QR - 1;
    const int tid = threadIdx.x, wid = tid >> 5, lane = tid & 31;
    const int grp = lane >> 2, tig = lane & 3;
    const int l8 = lane & 7, g8 = lane >> 3;
    const size_t bbase = (size_t)b * T_SZ;

    const int lo0 = max(0, r0 - (WIN - 1));
    const int gn  = min(NGLOB, r3 + 1);
    const int l0u = max(64, lo0);
    const int ln  = max(0, r3 - l0u + 1);
    const int nd  = gn + ln;
    const int ndt = (nd + 63) >> 6;

    for (int i = tid; i < QR * 64; i += 256) {
        QS[i] = g_Q[(bbase + r0 + (i >> 6)) * H_SZ + (i & 63)] * 0.125f;
        OR_[i] = 0.f;
        RBIT[i] = 0;
    }
    if (tid < 16) { rcnt[tid] = 0; l_r[tid] = 0.f; }
    __syncthreads();

    uint32_t aqh[4][4], aql[4][4];
#pragma unroll
    for (int ks = 0; ks < 4; ks++) {
        const float* qA = QS + grp * 64 + ks * 16 + 2 * tig;
        const float* qB = QS + (grp + 8) * 64 + ks * 16 + 2 * tig;
        split2(qA[0], qA[1], aqh[ks][0], aql[ks][0]);
        split2(qB[0], qB[1], aqh[ks][1], aql[ks][1]);
        split2(qA[8], qA[9], aqh[ks][2], aql[ks][2]);
        split2(qB[8], qB[9], aqh[ks][3], aql[ks][3]);
    }

    if (tid < gn) cols[tid] = (uint16_t)tid;
    if (tid >= 64 && tid < 64 + ln) cols[gn + tid - 64] = (uint16_t)(l0u + tid - 64);
    for (int i = tid; i < QR * NRAND; i += 256) {
        const int row = i >> 6;
        const int v = random_cols[(r0 + row) * NRAND + (i & 63)];
        const uint32_t bit = 1u << (v & 31);
        const uint32_t old = atomicOr(&RBIT[row * 64 + (v >> 5)], bit);
        if (v >= 64 && v < l0u && !(old & bit))
            rlist[row * 64 + atomicAdd(&rcnt[row], 1)] = (uint16_t)v;
    }
    __syncthreads();

    const int glc = tid >> 3;
    const int gch = (tid & 7) << 2;
#define GATHER(T) do {                                                        \
        const int _t0 = (T) << 6;                                             \
        _Pragma("unroll")                                                     \
        for (int _e = 0; _e < 2; _e++) {                                      \
            const int _lc = glc + _e * 32;                                    \
            const int _idx = _t0 + _lc;                                       \
            const int _cg = (_idx < nd) ? (int)cols[_idx] : 0;                \
            const size_t _gb = (bbase + _cg) * 32 + gch;                      \
            const int _so = _lc * KST + gch;                                  \
            cp16(&KH[_so], &g_Kh[_gb]);                                       \
            cp16(&KL[_so], &g_Kl[_gb]);                                       \
            cp16(&VH[_so], &g_Vh[_gb]);                                       \
            cp16(&VL[_so], &g_Vl[_gb]);                                       \
        }                                                                     \
        asm volatile("cp.async.commit_group;");                               \
        asm volatile("cp.async.wait_group 0;");                               \
    } while (0)

    GATHER(0);

    float oc0[4] = {0.f,0.f,0.f,0.f};
    float oc1[4] = {0.f,0.f,0.f,0.f};
    float oc2[4] = {0.f,0.f,0.f,0.f};
    float lA = 0.f, lB = 0.f;

    for (int t = 0; t < ndt; t++) {
        __syncthreads();

        // QK: 3 accumulator sets, one per split term
        float s0[4] = {0.f,0.f,0.f,0.f};
        float s1[4] = {0.f,0.f,0.f,0.f};
        float s2[4] = {0.f,0.f,0.f,0.f};
        const int kr = (wid << 3) + grp;
#pragma unroll
        for (int ks = 0; ks < 4; ks++) {
            const int o = kr * KST + (ks << 3) + tig;
            uint32_t bh[2] = { KH[o], KH[o + 4] };
            uint32_t bl[2] = { KL[o], KL[o + 4] };
            mma_bf16(s0, aql[ks], bh);
            mma_bf16(s1, aqh[ks], bl);
            mma_bf16(s2, aqh[ks], bh);
        }
        float sc[4];
#pragma unroll
        for (int j = 0; j < 4; j++) sc[j] = s0[j] + s1[j] + s2[j];

        const int iA = (t << 6) + (wid << 3) + (tig << 1);
        const int cA = (iA < nd) ? (int)cols[iA] : -1;
        const int cB = (iA + 1 < nd) ? (int)cols[iA + 1] : -1;
        const int rA = r0 + grp, rB = rA + 8;
#define OKM(r, c, rl) ((c) >= 0 && (c) <= (r) && ((c) > (r) - WIN || (c) < NGLOB || \
                       ((RBIT[(rl) * 64 + ((c) >> 5)] >> ((c) & 31)) & 1u)))
        const float p00 = OKM(rA, cA, grp)     ? __expf(sc[0] - SHIFT) : 0.f;
        const float p01 = OKM(rA, cB, grp)     ? __expf(sc[1] - SHIFT) : 0.f;
        const float p10 = OKM(rB, cA, grp + 8) ? __expf(sc[2] - SHIFT) : 0.f;
        const float p11 = OKM(rB, cB, grp + 8) ? __expf(sc[3] - SHIFT) : 0.f;
#undef OKM
        lA += p00 + p01;
        lB += p10 + p11;

        {
            const int w = (wid << 2) + tig;
            const int pp = ((w >> 3) << 3) + ((w & 3) << 1) + ((w >> 2) & 1);
            uint32_t hw, lw;
            split2(p00, p01, hw, lw);
            ph[grp][pp] = hw; pl[grp][pp] = lw;
            split2(p10, p11, hw, lw);
            ph[grp + 8][pp] = hw; pl[grp + 8][pp] = lw;
        }
        __syncthreads();

        // PV: 3 persistent accumulator sets
#pragma unroll
        for (int ks = 0; ks < 4; ks++) {
            uint32_t pah[4], pal[4];
            uint2 t0 = *(const uint2*)&ph[grp][(ks << 3) + (tig << 1)];
            uint2 t1 = *(const uint2*)&ph[grp + 8][(ks << 3) + (tig << 1)];
            pah[0] = t0.x; pah[2] = t0.y; pah[1] = t1.x; pah[3] = t1.y;
            uint2 t2 = *(const uint2*)&pl[grp][(ks << 3) + (tig << 1)];
            uint2 t3 = *(const uint2*)&pl[grp + 8][(ks << 3) + (tig << 1)];
            pal[0] = t2.x; pal[2] = t2.y; pal[1] = t3.x; pal[3] = t3.y;

            const int vo = ((ks << 4) + (lane & 15)) * KST + (wid << 2);
            uint32_t bvh[2], bvl[2];
            ldmx2t(bvh[0], bvh[1], (uint32_t)__cvta_generic_to_shared(&VH[vo]));
            ldmx2t(bvl[0], bvl[1], (uint32_t)__cvta_generic_to_shared(&VL[vo]));
            mma_bf16(oc0, pal, bvh);
            mma_bf16(oc1, pah, bvl);
            mma_bf16(oc2, pah, bvh);
        }
        __syncthreads();

        if (t + 1 < ndt) GATHER(t + 1);
    }

    float oc[4];
#pragma unroll
    for (int j = 0; j < 4; j++) oc[j] = oc0[j] + oc1[j] + oc2[j];

    // scalar phase: per-row random extras
#pragma unroll
    for (int half = 0; half < 2; half++) {
        const int rr = wid + half * 8;
        const int cnt = rcnt[rr];
        float qreg[8];
#pragma unroll
        for (int d = 0; d < 8; d++) qreg[d] = QS[rr * 64 + 8 * l8 + d];
        float o8[8] = {0.f,0.f,0.f,0.f,0.f,0.f,0.f,0.f};
        float lp = 0.f;

        for (int j0 = 0; j0 < cnt; j0 += 4) {
            const int j = j0 + g8;
            const bool act = (j < cnt);
            const int c = (int)rlist[rr * 64 + (act ? j : 0)];
            const size_t gb = (bbase + c) * 32 + 4 * l8;
            const uint4 khw = *(const uint4*)&g_Kh[gb];
            const uint4 klw = *(const uint4*)&g_Kl[gb];
            const uint4 vhw = *(const uint4*)&g_Vh[gb];
            const uint4 vlw = *(const uint4*)&g_Vl[gb];

            float p = qreg[0] * (bflo(khw.x) + bflo(klw.x))
                    + qreg[1] * (bfhi(khw.x) + bfhi(klw.x))
                    + qreg[2] * (bflo(khw.y) + bflo(klw.y))
                    + qreg[3] * (bfhi(khw.y) + bfhi(klw.y))
                    + qreg[4] * (bflo(khw.z) + bflo(klw.z))
                    + qreg[5] * (bfhi(khw.z) + bfhi(klw.z))
                    + qreg[6] * (bflo(khw.w) + bflo(klw.w))
                    + qreg[7] * (bfhi(khw.w) + bfhi(klw.w));
            p += __shfl_xor_sync(0xffffffffu, p, 1);
            p += __shfl_xor_sync(0xffffffffu, p, 2);
            p += __shfl_xor_sync(0xffffffffu, p, 4);
            const float wgt = act ? __expf(p - SHIFT) : 0.f;
            if (l8 == 0) lp += wgt;
            o8[0] += wgt * (bflo(vhw.x) + bflo(vlw.x));
            o8[1] += wgt * (bfhi(vhw.x) + bfhi(vlw.x));
            o8[2] += wgt * (bflo(vhw.y) + bflo(vlw.y));
            o8[3] += wgt * (bfhi(vhw.y) + bfhi(vlw.y));
            o8[4] += wgt * (bflo(vhw.z) + bflo(vlw.z));
            o8[5] += wgt * (bfhi(vhw.z) + bfhi(vlw.z));
            o8[6] += wgt * (bflo(vhw.w) + bflo(vlw.w));
            o8[7] += wgt * (bfhi(vhw.w) + bfhi(vlw.w));
        }
#pragma unroll
        for (int d = 0; d < 8; d++) {
            o8[d] += __shfl_xor_sync(0xffffffffu, o8[d], 8);
            o8[d] += __shfl_xor_sync(0xffffffffu, o8[d], 16);
        }
        lp += __shfl_xor_sync(0xffffffffu, lp, 8);
        lp += __shfl_xor_sync(0xffffffffu, lp, 16);
        if (g8 == 0) {
#pragma unroll
            for (int d = 0; d < 8; d++) OR_[rr * 64 + 8 * l8 + d] = o8[d];
            if (l8 == 0) l_r[rr] = lp;
        }
    }

    lA += __shfl_xor_sync(0xffffffffu, lA, 1);
    lA += __shfl_xor_sync(0xffffffffu, lA, 2);
    lB += __shfl_xor_sync(0xffffffffu, lB, 1);
    lB += __shfl_xor_sync(0xffffffffu, lB, 2);
    if (tig == 0) { lred[wid][grp] = lA; lred[wid][grp + 8] = lB; }
    __syncthreads();

    float sA = l_r[grp], sB = l_r[grp + 8];
#pragma unroll
    for (int w2 = 0; w2 < 8; w2++) { sA += lred[w2][grp]; sB += lred[w2][grp + 8]; }

    const int dim = (wid << 3) + (tig << 1);
    const float iA2 = 1.f / sA, iB2 = 1.f / sB;
    *(float2*)&out[(bbase + r0 + grp) * H_SZ + dim] =
        make_float2((oc[0] + OR_[grp * 64 + dim]) * iA2,
                    (oc[1] + OR_[grp * 64 + dim + 1]) * iA2);
    *(float2*)&out[(bbase + r0 + grp + 8) * H_SZ + dim] =
        make_float2((oc[2] + OR_[(grp + 8) * 64 + dim]) * iB2,
                    (oc[3] + OR_[(grp + 8) * 64 + dim + 1]) * iB2);
}

// ---------------------------------------------------------------------------
// kernel_launch — inputs per metadata order: x, random_cols, Wk, Wq, Wv
// ---------------------------------------------------------------------------
extern "C" void kernel_launch(void* const* d_in, const int* in_sizes, int n_in,
                              void* d_out, int out_size)
{
    const float* x           = (const float*)d_in[0];
    const int*   random_cols = (const int*)  d_in[1];
    const float* Wk          = (const float*)d_in[2];
    const float* Wq          = (const float*)d_in[3];
    const float* Wv          = (const float*)d_in[4];
    float* out = (float*)d_out;

    static bool attr_set = false;
    if (!attr_set) {
        cudaFuncSetAttribute(attn16_kernel,
                             cudaFuncAttributeMaxDynamicSharedMemorySize,
                             SMEM_ATTN);
        attr_set = true;
    }

    proj_tc_kernel<<<BT / 64, 256>>>(x, Wq, Wk, Wv);
    attn16_kernel<<<BT / QR, 256, SMEM_ATTN>>>(random_cols, out);
}